// round 12
// baseline (speedup 1.0000x reference)
#include <cuda_runtime.h>
#include <cuda_bf16.h>
#include <cstdint>
#include <cstddef>

#define DINL __device__ __forceinline__

// ---------------------------------------------------------------------------
// HoMESecondLayer v12: 33-step chunk pipeline, 3-buffer cp.async ring with
// depth-2 prefetch (wait_group 1), one barrier per step. ROWS=128/512thr.
// ---------------------------------------------------------------------------

constexpr int ROWS    = 128;
constexpr int THREADS = 512;
constexpr int META    = 128;
constexpr int GIN     = 256;

// bf16 weight images: W^T as [N][K], row-major K-contiguous.
constexpr int IW1 = 0;                    // 6 x [128][256]
constexpr int IW2 = IW1 + 6 * 128 * 256;  // 6 x [64][128]
constexpr int IW3 = IW2 + 6 * 64 * 128;   // 6 x [64][64]
constexpr int ITG = IW3 + 6 * 64 * 64;    // 4 x [64][256]
constexpr int IT1 = ITG + 4 * 64 * 256;   // 4 x [64][64]
constexpr int ITOT = IT1 + 4 * 64 * 64;
__device__ __align__(16) __nv_bfloat16 g_wimg[ITOT];

// smem layout (byte offsets)
constexpr int RING_B   = 18432;            // 128 rows x 9 uint4
constexpr int OFF_RING = 0;                // 3 bufs = 55296
constexpr int OFF_A    = 55296;            // aw: bf16 words 128*68 = 34816
constexpr int OFF_B    = 90112;            // bw: bf16 words 128*36 = 18432
constexpr int OFF_CFP  = 108544;           // cfp: float 128*66 = 33792
constexpr int OFF_CMB  = 142336;           // cmw: bf16 words 128*132 = 67584
constexpr int OFF_GW   = 209920;           // float 128*4 = 2048
constexpr int SMEM_TOTAL = 211968;
constexpr int SLAB_BYTES = 18432;          // gating slabs overlay OFF_A..

// pitches
constexpr int P_CM = 132;  // words; 33*16B, 33%8=1 -> LDSM conflict-free
constexpr int P_A  = 68;   // 17*16B
constexpr int P_B  = 36;   // 9*16B
constexpr int P_CF = 66;   // floats
constexpr int P_SL = 36;   // slab pitch (floats)

DINL float tanh_ap(float x) {
    float y; asm("tanh.approx.f32 %0, %1;" : "=f"(y) : "f"(x)); return y;
}
DINL float sigm(float x)   { return fmaf(tanh_ap(0.5f * x), 0.5f, 0.5f); }
DINL float swishf(float x) { return x * sigm(x); }
DINL uint32_t sm_addr(const void* p) {
    return (uint32_t)__cvta_generic_to_shared(p);
}
DINL void mma16(float* d, const uint32_t* a, uint32_t b0, uint32_t b1) {
    asm volatile(
        "mma.sync.aligned.m16n8k16.row.col.f32.bf16.bf16.f32 "
        "{%0,%1,%2,%3},{%4,%5,%6,%7},{%8,%9},{%0,%1,%2,%3};"
        : "+f"(d[0]), "+f"(d[1]), "+f"(d[2]), "+f"(d[3])
        : "r"(a[0]), "r"(a[1]), "r"(a[2]), "r"(a[3]), "r"(b0), "r"(b1));
}
DINL void ldsm4(uint32_t& r0, uint32_t& r1, uint32_t& r2, uint32_t& r3,
                uint32_t addr) {
    asm volatile(
        "ldmatrix.sync.aligned.m8n8.x4.shared.b16 {%0,%1,%2,%3}, [%4];"
        : "=r"(r0), "=r"(r1), "=r"(r2), "=r"(r3) : "r"(addr));
}
DINL uint32_t packbf(float lo, float hi) {
    __nv_bfloat162 p = __floats2bfloat162_rn(lo, hi);
    return *reinterpret_cast<uint32_t*>(&p);
}
DINL float2 unpkbf(uint32_t w) {
    __nv_bfloat162 b = *reinterpret_cast<__nv_bfloat162*>(&w);
    return __bfloat1622float2(b);
}
DINL void cp16(uint32_t dst, const void* src) {
    asm volatile("cp.async.cg.shared.global [%0], [%1], 16;"
                 :: "r"(dst), "l"(src));
}
DINL void cp_commit() { asm volatile("cp.async.commit_group;" ::: "memory"); }
DINL void cp_wait0()  { asm volatile("cp.async.wait_group 0;" ::: "memory"); }
DINL void cp_wait1()  { asm volatile("cp.async.wait_group 1;" ::: "memory"); }

// ---- single merged prep: all W[K][N] fp32 -> bf16 W^T [N][K] images -------
__global__ void prep_all(const float* __restrict__ eW1,
                         const float* __restrict__ eW2,
                         const float* __restrict__ eW3,
                         const float* __restrict__ tgW1,
                         const float* __restrict__ twW1)
{
    const int SZ1 = 6 * 128 * 256, SZ2 = 6 * 64 * 128, SZ3 = 6 * 64 * 64;
    const int SZ4 = 4 * 64 * 256,  SZ5 = 4 * 64 * 64;
    const int total = SZ1 + SZ2 + SZ3 + SZ4 + SZ5;
    for (int gi = blockIdx.x * blockDim.x + threadIdx.x; gi < total;
         gi += gridDim.x * blockDim.x) {
        int idx = gi, dstOff, K, N;
        const float* src;
        if (idx < SZ1)                 { dstOff = IW1; src = eW1;  K = 256; N = 128; }
        else if ((idx -= SZ1) < SZ2)   { dstOff = IW2; src = eW2;  K = 128; N = 64; }
        else if ((idx -= SZ2) < SZ3)   { dstOff = IW3; src = eW3;  K = 64;  N = 64; }
        else if ((idx -= SZ3) < SZ4)   { dstOff = ITG; src = tgW1; K = 256; N = 64; }
        else         { idx -= SZ4;       dstOff = IT1; src = twW1; K = 64;  N = 64; }
        const int m   = idx / (K * N);
        const int rem = idx - m * (K * N);
        const int n   = rem / K;
        const int k   = rem - n * K;
        g_wimg[dstOff + idx] = __float2bfloat16(src[(size_t)m * K * N + k * N + n]);
    }
}

// ---- dynamic chunk descriptor: stage chunk `cid` into ring buffer ---------
// Chunk map (all 64-K, P16=9):
//   0..3   : TG  (rows 64,  KU 32, kc = cid)
//   4+7e+r : r<4 -> W1 e (rows 128, KU 32, kc=r); r<6 -> W2 e (rows 64, KU 16,
//            kc=r-4); r==6 -> W3 e (rows 64, KU 8, kc=0)
//   32     : T1  (rows 64,  KU 8,  kc = 0)
DINL void stage_dyn(int cid, int t, int g, uint32_t buf, int tid)
{
    const __nv_bfloat16* ptr; int rows, KU, kc;
    if (cid < 4)      { ptr = g_wimg + ITG + t * 16384; rows = 64;  KU = 32; kc = cid; }
    else if (cid < 32) {
        const int c2 = cid - 4;
        const int ep = c2 / 7;
        const int r  = c2 - ep * 7;
        const int e  = (ep < 2) ? ep : (ep + 2 * g);
        if (r < 4)      { ptr = g_wimg + IW1 + e * 32768; rows = 128; KU = 32; kc = r; }
        else if (r < 6) { ptr = g_wimg + IW2 + e * 8192;  rows = 64;  KU = 16; kc = r - 4; }
        else            { ptr = g_wimg + IW3 + e * 4096;  rows = 64;  KU = 8;  kc = 0; }
    } else            { ptr = g_wimg + IT1 + t * 4096;  rows = 64;  KU = 8;  kc = 0; }

    const uint4* gsrc = reinterpret_cast<const uint4*>(ptr);
    const int units = rows >> 6;   // rows*8/512
    for (int j = 0; j < units; j++) {
        const int i = tid + j * THREADS;
        cp16(buf + (uint32_t)((i >> 3) * 9 + (i & 7)) * 16,
             gsrc + (i >> 3) * KU + kc * 8 + (i & 7));
    }
    cp_commit();
}

// ---- pipeline step head: retire chunk i, publish, prefetch i+2 ------------
DINL void pipe_head(int i, int t, int g, const uint32_t* bufA, int tid)
{
    if (i >= 32) cp_wait0(); else cp_wait1();
    __syncthreads();
    if (i + 2 <= 32) stage_dyn(i + 2, t, g, bufA[(i + 2) % 3], tid);
}

// ---- MMA over one 64-K staged chunk ---------------------------------------
template<int N, int AP2>
DINL void mma_chunk(float acc[][4][4], const uint32_t* As, uint32_t buf,
                    int kc, int tid)
{
    constexpr int WN = (N >= 128) ? 4 : 2;
    constexpr int MT = (N >= 128) ? 2 : 1;
    const int w = tid >> 5, lane = tid & 31;
    const int col0  = (w % WN) * 32;
    const int mrow0 = (w / WN) * (MT * 16);
    const int lrow = lane & 7, lg8 = (lane >> 3) & 1, lg16 = lane >> 4;

    const uint32_t abase = sm_addr(As);
    uint32_t a_addr[MT];
#pragma unroll
    for (int mt = 0; mt < MT; mt++)
        a_addr[mt] = abase +
            ((mrow0 + mt * 16 + lg8 * 8 + lrow) * AP2 + lg16 * 4) * 4;
    uint32_t b_addr[2];
#pragma unroll
    for (int p = 0; p < 2; p++)
        b_addr[p] = buf +
            (uint32_t)(col0 + p * 16 + lg16 * 8 + lrow) * 144 + lg8 * 16;

#pragma unroll
    for (int ks2 = 0; ks2 < 4; ks2++) {
        const int ksg = kc * 4 + ks2;
        uint32_t af[MT][4];
#pragma unroll
        for (int mt = 0; mt < MT; mt++)
            ldsm4(af[mt][0], af[mt][1], af[mt][2], af[mt][3],
                  a_addr[mt] + ksg * 32);
        uint32_t bf[4][2];
#pragma unroll
        for (int p = 0; p < 2; p++)
            ldsm4(bf[2 * p][0], bf[2 * p][1], bf[2 * p + 1][0], bf[2 * p + 1][1],
                  b_addr[p] + ks2 * 32);
#pragma unroll
        for (int nt = 0; nt < 4; nt++)
#pragma unroll
            for (int mt = 0; mt < MT; mt++)
                mma16(acc[mt][nt], af[mt], bf[nt][0], bf[nt][1]);
    }
}

// ---- epilogue: bias (+swish), store fp32 or packed bf16 -------------------
template<int N, bool SW, bool OUTBF, int CP>
DINL void epilogue(float acc[][4][4], const float* __restrict__ bias,
                   void* Cs, int tid)
{
    constexpr int WN = (N >= 128) ? 4 : 2;
    constexpr int MT = (N >= 128) ? 2 : 1;
    const int w = tid >> 5, lane = tid & 31;
    const int col0  = (w % WN) * 32;
    const int mrow0 = (w / WN) * (MT * 16);
    const int r = lane >> 2, c = lane & 3;
#pragma unroll
    for (int mt = 0; mt < MT; mt++) {
        const int row = mrow0 + mt * 16 + r;
#pragma unroll
        for (int nt = 0; nt < 4; nt++) {
            const int cn = col0 + nt * 8 + 2 * c;
            const float bb0 = __ldg(&bias[cn]), bb1 = __ldg(&bias[cn + 1]);
            float v0 = acc[mt][nt][0] + bb0, v1 = acc[mt][nt][1] + bb1;
            float v2 = acc[mt][nt][2] + bb0, v3 = acc[mt][nt][3] + bb1;
            if (SW) { v0 = swishf(v0); v1 = swishf(v1); v2 = swishf(v2); v3 = swishf(v3); }
            if (OUTBF) {
                uint32_t* C = reinterpret_cast<uint32_t*>(Cs);
                C[row * CP + (cn >> 1)]       = packbf(v0, v1);
                C[(row + 8) * CP + (cn >> 1)] = packbf(v2, v3);
            } else {
                float* C = reinterpret_cast<float*>(Cs);
                C[row * CP + cn] = v0; C[row * CP + cn + 1] = v1;
                C[(row + 8) * CP + cn] = v2; C[(row + 8) * CP + cn + 1] = v3;
            }
        }
    }
}

// small SIMT gemm for tower layer 2 (N=32)
DINL void gemm_t2(const float* As, const float* __restrict__ Wg,
                  const float* __restrict__ bg, float* Cs, int tid)
{
    constexpr int CT = 8, TM = 2;
    const int tc = tid % CT, tr = tid / CT;
    const int col = tc * 4;
    float acc[TM][4];
#pragma unroll
    for (int m = 0; m < TM; m++) {
        acc[m][0] = 0.f; acc[m][1] = 0.f; acc[m][2] = 0.f; acc[m][3] = 0.f;
    }
    for (int k = 0; k < 64; k++) {
        const float4 wv = __ldg(reinterpret_cast<const float4*>(Wg + (size_t)k * 32 + col));
#pragma unroll
        for (int m = 0; m < TM; m++) {
            const float a = As[(tr * TM + m) * P_CF + k];
            acc[m][0] = fmaf(a, wv.x, acc[m][0]);
            acc[m][1] = fmaf(a, wv.y, acc[m][1]);
            acc[m][2] = fmaf(a, wv.z, acc[m][2]);
            acc[m][3] = fmaf(a, wv.w, acc[m][3]);
        }
    }
    const float4 bv = __ldg(reinterpret_cast<const float4*>(bg + col));
#pragma unroll
    for (int m = 0; m < TM; m++) {
        float* cp = Cs + (tr * TM + m) * P_B + col;
        cp[0] = swishf(acc[m][0] + bv.x);
        cp[1] = swishf(acc[m][1] + bv.y);
        cp[2] = swishf(acc[m][2] + bv.z);
        cp[3] = swishf(acc[m][3] + bv.w);
    }
}

__global__ __launch_bounds__(THREADS, 1)
void home_kernel(
    const float* __restrict__ z_shared, const float* __restrict__ z_g0,
    const float* __restrict__ z_g1,
    const float* __restrict__ exp_b1, const float* __restrict__ exp_b2,
    const float* __restrict__ exp_b3,
    const float* __restrict__ ln_s,   const float* __restrict__ ln_b,
    const float* __restrict__ fg_A,   const float* __restrict__ fg_B,
    const float* __restrict__ tg_b1,
    const float* __restrict__ tg_W2,  const float* __restrict__ tg_b2,
    const float* __restrict__ sg_W,   const float* __restrict__ sg_b,
    const float* __restrict__ tw_b1,
    const float* __restrict__ tw_W2,  const float* __restrict__ tw_b2,
    const float* __restrict__ tw_W3,  const float* __restrict__ tw_b3,
    float* __restrict__ out)
{
    extern __shared__ char sm[];
    float*    fga   = reinterpret_cast<float*>(sm + OFF_CFP);          // [256][8]
    float*    fgb   = reinterpret_cast<float*>(sm + OFF_CFP + 8192);   // [8][256]
    float*    slab0 = reinterpret_cast<float*>(sm + OFF_A);
    float*    slab1 = reinterpret_cast<float*>(sm + OFF_A + SLAB_BYTES);
    uint32_t* cmw   = reinterpret_cast<uint32_t*>(sm + OFF_CMB);
    uint32_t* aw    = reinterpret_cast<uint32_t*>(sm + OFF_A);
    uint32_t* bw    = reinterpret_cast<uint32_t*>(sm + OFF_B);
    float*    cfp   = reinterpret_cast<float*>(sm + OFF_CFP);
    float*    gwb   = reinterpret_cast<float*>(sm + OFF_GW);
    float*    lgb   = reinterpret_cast<float*>(sm + OFF_B);
    float*    twh2  = reinterpret_cast<float*>(sm + OFF_B);

    const uint32_t bufA[3] = { sm_addr(sm + OFF_RING),
                               sm_addr(sm + OFF_RING + RING_B),
                               sm_addr(sm + OFF_RING + 2 * RING_B) };

    const int tid  = threadIdx.x;
    const int wid  = tid >> 5, lane = tid & 31;
    const int t    = blockIdx.y;
    const int g    = t >> 1;                    // TASK_TO_GROUP = {0,0,1,1}
    const int row0 = blockIdx.x * ROWS;
    const float* zg = g ? z_g1 : z_g0;

    // ---- prefetch chunks 0,1 (TG) — overlap all of gating -----------------
    stage_dyn(0, t, g, bufA[0], tid);
    stage_dyn(1, t, g, bufA[1], tid);

    // ---- stage fgA [256][8], fgB [8][256] into smem ------------------------
    {
        const float4* A4 = reinterpret_cast<const float4*>(fg_A + (size_t)t * 2048);
        const float4* B4 = reinterpret_cast<const float4*>(fg_B + (size_t)t * 2048);
        reinterpret_cast<float4*>(fga)[tid] = __ldg(&A4[tid]);
        reinterpret_cast<float4*>(fgb)[tid] = __ldg(&B4[tid]);
    }

    // ---- gating pass 1: double-buffered slab; racc; pack UNGATED cm -------
    const int grow = tid >> 2;
    const int jp   = (tid & 3) * 2;
    float r0 = 0.f, r1 = 0.f;
#pragma unroll
    for (int j = 0; j < 2; j++) {
        const int i = tid + j * THREADS;
        *reinterpret_cast<float4*>(&slab0[(i >> 3) * P_SL + (i & 7) * 4]) =
            *reinterpret_cast<const float4*>(
                z_shared + (size_t)(row0 + (i >> 3)) * META + (i & 7) * 4);
    }
#pragma unroll 1
    for (int ch = 0; ch < 8; ch++) {
        __syncthreads();
        const float* cur = (ch & 1) ? slab1 : slab0;
        float4 zr[2];
        const bool more = (ch < 7);
        if (more) {
            const float* zsrc = (ch + 1 < 4) ? z_shared : zg;
            const int cb = ((ch + 1) & 3) * 32;
#pragma unroll
            for (int j = 0; j < 2; j++) {
                const int i = tid + j * THREADS;
                zr[j] = *reinterpret_cast<const float4*>(
                    zsrc + (size_t)(row0 + (i >> 3)) * META + cb + (i & 7) * 4);
            }
        }
#pragma unroll 8
        for (int k = 0; k < 32; k++) {
            const float a = cur[grow * P_SL + k];
            const float2 f = *reinterpret_cast<const float2*>(
                &fga[(ch * 32 + k) * 8 + jp]);
            r0 = fmaf(a, f.x, r0);
            r1 = fmaf(a, f.y, r1);
        }
#pragma unroll
        for (int i2 = 0; i2 < 4; i2++) {
            const int p = tid + i2 * THREADS;
            const int row = p >> 4, pp = p & 15;
            const float2 v = *reinterpret_cast<const float2*>(
                &cur[row * P_SL + 2 * pp]);
            cmw[row * P_CM + ch * 16 + pp] = packbf(v.x, v.y);
        }
        if (more) {
            float* nxt = (ch & 1) ? slab0 : slab1;
#pragma unroll
            for (int j = 0; j < 2; j++) {
                const int i = tid + j * THREADS;
                *reinterpret_cast<float4*>(&nxt[(i >> 3) * P_SL + (i & 7) * 4]) = zr[j];
            }
        }
    }
    float rr[8];
    {
        const int lb = lane & ~3;
#pragma unroll
        for (int k2 = 0; k2 < 4; k2++) {
            rr[2 * k2]     = __shfl_sync(0xffffffffu, r0, lb + k2);
            rr[2 * k2 + 1] = __shfl_sync(0xffffffffu, r1, lb + k2);
        }
    }
    __syncthreads();

    // ---- gating pass 2: gate cmw in place ----------------------------------
    {
        uint32_t* cmrow = cmw + grow * P_CM;
        const int cb4 = (tid & 3) * 8;
#pragma unroll
        for (int u = 0; u < 8; u++) {
            const int i4 = cb4 + u;
            uint4 w4 = *reinterpret_cast<uint4*>(cmrow + i4 * 4);
            const float2 v0 = unpkbf(w4.x), v1 = unpkbf(w4.y);
            const float2 v2 = unpkbf(w4.z), v3 = unpkbf(w4.w);
            float d[8];
#pragma unroll
            for (int q = 0; q < 8; q++) d[q] = 0.f;
#pragma unroll
            for (int j = 0; j < 8; j++) {
                const float rj = rr[j];
                const float4 f0 = *reinterpret_cast<const float4*>(&fgb[j * 256 + i4 * 8]);
                const float4 f1 = *reinterpret_cast<const float4*>(&fgb[j * 256 + i4 * 8 + 4]);
                d[0] = fmaf(rj, f0.x, d[0]); d[1] = fmaf(rj, f0.y, d[1]);
                d[2] = fmaf(rj, f0.z, d[2]); d[3] = fmaf(rj, f0.w, d[3]);
                d[4] = fmaf(rj, f1.x, d[4]); d[5] = fmaf(rj, f1.y, d[5]);
                d[6] = fmaf(rj, f1.z, d[6]); d[7] = fmaf(rj, f1.w, d[7]);
            }
            uint4 o;
            o.x = packbf(v0.x * 2.0f * sigm(d[0]), v0.y * 2.0f * sigm(d[1]));
            o.y = packbf(v1.x * 2.0f * sigm(d[2]), v1.y * 2.0f * sigm(d[3]));
            o.z = packbf(v2.x * 2.0f * sigm(d[4]), v2.y * 2.0f * sigm(d[5]));
            o.w = packbf(v3.x * 2.0f * sigm(d[6]), v3.y * 2.0f * sigm(d[7]));
            *reinterpret_cast<uint4*>(cmrow + i4 * 4) = o;
        }
    }
    // published by step-0's barrier

    // ---- steps 0..3: task-gate GEMM ----------------------------------------
    float accT[1][4][4];
#pragma unroll
    for (int nt = 0; nt < 4; nt++)
#pragma unroll
        for (int i = 0; i < 4; i++) accT[0][nt][i] = 0.f;
#pragma unroll 1
    for (int c = 0; c < 4; c++) {
        pipe_head(c, t, g, bufA, tid);
        mma_chunk<64, P_CM>(accT, cmw, bufA[c % 3], c, tid);
    }
    epilogue<64, true, false, P_CF>(accT, tg_b1 + t * 64, cfp, tid);

    // ---- expert loop: steps 4..31 ------------------------------------------
    int step = 4;
    float ag0[8], ag1[8];
#pragma unroll 1
    for (int ep = 0; ep < 4; ep++) {
        const int e = (ep < 2) ? ep : (ep + 2 * g);

        // W1: 4 chunks
        float acc1[2][4][4];
#pragma unroll
        for (int mt = 0; mt < 2; mt++)
#pragma unroll
            for (int nt = 0; nt < 4; nt++)
#pragma unroll
                for (int i = 0; i < 4; i++) acc1[mt][nt][i] = 0.f;
#pragma unroll 1
        for (int c = 0; c < 4; c++) {
            pipe_head(step, t, g, bufA, tid);
            if (step == 4) {           // logits (reads cfp published this bar)
                const int row = tid >> 2, j = tid & 3;
                const float* W = tg_W2 + (size_t)t * 64 * 4;
                float acc = __ldg(&tg_b2[t * 4 + j]);
#pragma unroll 4
                for (int c2 = 0; c2 < 64; c2++)
                    acc = fmaf(cfp[row * P_CF + c2], __ldg(&W[c2 * 4 + j]), acc);
                lgb[row * 4 + j] = acc;
            }
            if (step == 5) {           // softmax (reads lgb published this bar)
                if (tid < ROWS) {
                    const float l0 = lgb[tid * 4 + 0], l1 = lgb[tid * 4 + 1];
                    const float l2 = lgb[tid * 4 + 2], l3 = lgb[tid * 4 + 3];
                    const float m  = fmaxf(fmaxf(l0, l1), fmaxf(l2, l3));
                    const float e0 = __expf(l0 - m), e1 = __expf(l1 - m);
                    const float e2 = __expf(l2 - m), e3 = __expf(l3 - m);
                    const float inv = 1.0f / (e0 + e1 + e2 + e3);
                    gwb[tid * 4 + 0] = e0 * inv; gwb[tid * 4 + 1] = e1 * inv;
                    gwb[tid * 4 + 2] = e2 * inv; gwb[tid * 4 + 3] = e3 * inv;
                }
            }
            if (ep > 0 && c == 0) {    // LN of previous expert (cfp published)
                const int epp = ep - 1;
                const int epv = (epp < 2) ? epp : (epp + 2 * g);
                const float* lS  = ln_s + epv * 64;
                const float* lB  = ln_b + epv * 64;
                const float* sgw = sg_W + (size_t)t * 256;
                const float  sgb = __ldg(&sg_b[t * 4 + epp]);
                const int c0 = 2 * lane, c1 = 2 * lane + 1;
#pragma unroll
                for (int rw = 0; rw < 8; rw++) {
                    const int row = wid * 8 + rw;
                    const float2 v = *reinterpret_cast<const float2*>(&cfp[row * P_CF + c0]);
                    float sum = v.x + v.y;
                    float sq  = fmaf(v.x, v.x, v.y * v.y);
#pragma unroll
                    for (int o = 16; o; o >>= 1) {
                        sum += __shfl_xor_sync(0xffffffffu, sum, o);
                        sq  += __shfl_xor_sync(0xffffffffu, sq,  o);
                    }
                    const float mu  = sum * (1.0f / 64.0f);
                    const float var = sq * (1.0f / 64.0f) - mu * mu;
                    const float inv = rsqrtf(var + 1e-5f);
                    const float n0  = fmaf((v.x - mu) * inv, __ldg(&lS[c0]), __ldg(&lB[c0]));
                    const float n1  = fmaf((v.y - mu) * inv, __ldg(&lS[c1]), __ldg(&lB[c1]));
                    float swp = fmaf(n0, __ldg(&sgw[c0 * 4 + epp]),
                                     n1 * __ldg(&sgw[c1 * 4 + epp]));
#pragma unroll
                    for (int o = 16; o; o >>= 1)
                        swp += __shfl_xor_sync(0xffffffffu, swp, o);
                    const float scale = (swp + sgb) * gwb[row * 4 + epp];
                    if (epp == 0) { ag0[rw] = n0 * scale;                ag1[rw] = n1 * scale; }
                    else          { ag0[rw] = fmaf(n0, scale, ag0[rw]);  ag1[rw] = fmaf(n1, scale, ag1[rw]); }
                }
            }
            mma_chunk<128, P_CM>(acc1, cmw, bufA[step % 3], c, tid);
            step++;
        }
        epilogue<128, true, true, P_A>(acc1, exp_b1 + e * 128, aw, tid);

        // W2: 2 chunks
        float acc2[1][4][4];
#pragma unroll
        for (int nt = 0; nt < 4; nt++)
#pragma unroll
            for (int i = 0; i < 4; i++) acc2[0][nt][i] = 0.f;
#pragma unroll 1
        for (int c = 0; c < 2; c++) {
            pipe_head(step, t, g, bufA, tid);
            mma_chunk<64, P_A>(acc2, aw, bufA[step % 3], c, tid);
            step++;
        }
        epilogue<64, true, true, P_B>(acc2, exp_b2 + e * 64, bw, tid);

        // W3: 1 chunk
        float acc3[1][4][4];
#pragma unroll
        for (int nt = 0; nt < 4; nt++)
#pragma unroll
            for (int i = 0; i < 4; i++) acc3[0][nt][i] = 0.f;
        pipe_head(step, t, g, bufA, tid);
        mma_chunk<64, P_B>(acc3, bw, bufA[step % 3], 0, tid);
        step++;
        epilogue<64, false, false, P_CF>(acc3, exp_b3 + e * 64, cfp, tid);
    }

    // ---- step 32: LN(e3) + agg handoff + tower layer 1 ---------------------
    pipe_head(32, t, g, bufA, tid);
    {   // LN for expert 3 (cfp published by this bar)
        const int epp = 3;
        const int epv = 3 + 2 * g;
        const float* lS  = ln_s + epv * 64;
        const float* lB  = ln_b + epv * 64;
        const float* sgw = sg_W + (size_t)t * 256;
        const float  sgb = __ldg(&sg_b[t * 4 + epp]);
        const int c0 = 2 * lane, c1 = 2 * lane + 1;
#pragma unroll
        for (int rw = 0; rw < 8; rw++) {
            const int row = wid * 8 + rw;
            const float2 v = *reinterpret_cast<const float2*>(&cfp[row * P_CF + c0]);
            float sum = v.x + v.y;
            float sq  = fmaf(v.x, v.x, v.y * v.y);
#pragma unroll
            for (int o = 16; o; o >>= 1) {
                sum += __shfl_xor_sync(0xffffffffu, sum, o);
                sq  += __shfl_xor_sync(0xffffffffu, sq,  o);
            }
            const float mu  = sum * (1.0f / 64.0f);
            const float var = sq * (1.0f / 64.0f) - mu * mu;
            const float inv = rsqrtf(var + 1e-5f);
            const float n0  = fmaf((v.x - mu) * inv, __ldg(&lS[c0]), __ldg(&lB[c0]));
            const float n1  = fmaf((v.y - mu) * inv, __ldg(&lS[c1]), __ldg(&lB[c1]));
            float swp = fmaf(n0, __ldg(&sgw[c0 * 4 + epp]),
                             n1 * __ldg(&sgw[c1 * 4 + epp]));
#pragma unroll
            for (int o = 16; o; o >>= 1)
                swp += __shfl_xor_sync(0xffffffffu, swp, o);
            const float scale = (swp + sgb) * gwb[row * 4 + epp];
            ag0[rw] = fmaf(n0, scale, ag0[rw]);
            ag1[rw] = fmaf(n1, scale, ag1[rw]);
        }
    }
#pragma unroll
    for (int rw = 0; rw < 8; rw++) {
        const int row = wid * 8 + rw;
        bw[row * P_B + lane] = packbf(ag0[rw], ag1[rw]);
    }
    __syncthreads();   // publish agg before T1 mma reads cross-warp

    float accU[1][4][4];
#pragma unroll
    for (int nt = 0; nt < 4; nt++)
#pragma unroll
        for (int i = 0; i < 4; i++) accU[0][nt][i] = 0.f;
    mma_chunk<64, P_B>(accU, bw, bufA[32 % 3], 0, tid);
    epilogue<64, true, false, P_CF>(accU, tw_b1 + t * 64, cfp, tid);
    __syncthreads();
    gemm_t2(cfp, tw_W2 + (size_t)t * 64 * 32, tw_b2 + t * 32, twh2, tid);
    __syncthreads();
    if (tid < ROWS) {
        const float* th = &twh2[tid * P_B];
        const float* W  = tw_W3 + t * 32;
        float acc = __ldg(&tw_b3[t]);
#pragma unroll 4
        for (int c2 = 0; c2 < 32; c2++)
            acc = fmaf(th[c2], __ldg(&W[c2]), acc);
        out[(size_t)(row0 + tid) * 4 + t] = sigm(acc);
    }
}

extern "C" void kernel_launch(void* const* d_in, const int* in_sizes, int n_in,
                              void* d_out, int out_size)
{
    (void)n_in; (void)out_size;
    const float* zs   = (const float*)d_in[0];
    const float* z0   = (const float*)d_in[1];
    const float* z1   = (const float*)d_in[2];
    const float* eW1  = (const float*)d_in[4];
    const float* eb1  = (const float*)d_in[5];
    const float* eW2  = (const float*)d_in[6];
    const float* eb2  = (const float*)d_in[7];
    const float* eW3  = (const float*)d_in[8];
    const float* eb3  = (const float*)d_in[9];
    const float* lns  = (const float*)d_in[10];
    const float* lnb  = (const float*)d_in[11];
    const float* fgA  = (const float*)d_in[12];
    const float* fgB  = (const float*)d_in[13];
    const float* tgW1 = (const float*)d_in[14];
    const float* tgb1 = (const float*)d_in[15];
    const float* tgW2 = (const float*)d_in[16];
    const float* tgb2 = (const float*)d_in[17];
    const float* sgW  = (const float*)d_in[18];
    const float* sgb  = (const float*)d_in[19];
    const float* twW1 = (const float*)d_in[20];
    const float* twb1 = (const float*)d_in[21];
    const float* twW2 = (const float*)d_in[22];
    const float* twb2 = (const float*)d_in[23];
    const float* twW3 = (const float*)d_in[24];
    const float* twb3 = (const float*)d_in[25];

    const int Bn = in_sizes[0] / META;

    prep_all<<<296, 256>>>(eW1, eW2, eW3, tgW1, twW1);

    cudaFuncSetAttribute(home_kernel, cudaFuncAttributeMaxDynamicSharedMemorySize,
                         SMEM_TOTAL);
    dim3 grid(Bn / ROWS, 4);
    home_kernel<<<grid, THREADS, SMEM_TOTAL>>>(
        zs, z0, z1, eb1, eb2, eb3, lns, lnb, fgA, fgB,
        tgb1, tgW2, tgb2, sgW, sgb, twb1, twW2, twb2, twW3, twb3,
        (float*)d_out);
}

// round 13
// speedup vs baseline: 1.1280x; 1.1280x over previous
#include <cuda_runtime.h>
#include <cuda_bf16.h>
#include <cstdint>
#include <cstddef>

#define DINL __device__ __forceinline__

// ---------------------------------------------------------------------------
// HoMESecondLayer v13: R11 base (best) + merged W2/W3 staging step.
// ROWS=128 / 512 threads / 1 CTA per SM; bf16 mma.m16n8k16 + ldmatrix;
// cp.async double-buffered weight ring; tanh activations; vectorized gating.
// ---------------------------------------------------------------------------

constexpr int ROWS    = 128;
constexpr int THREADS = 512;
constexpr int META    = 128;
constexpr int GIN     = 256;

// bf16 weight images: W^T as [N][K], row-major K-contiguous.
constexpr int IW1 = 0;                    // 6 x [128][256]
constexpr int IW2 = IW1 + 6 * 128 * 256;  // 6 x [64][128]
constexpr int IW3 = IW2 + 6 * 64 * 128;   // 6 x [64][64]
constexpr int ITG = IW3 + 6 * 64 * 64;    // 4 x [64][256]
constexpr int IT1 = ITG + 4 * 64 * 256;   // 4 x [64][64]
constexpr int ITOT = IT1 + 4 * 64 * 64;
__device__ __align__(16) __nv_bfloat16 g_wimg[ITOT];

// smem layout (byte offsets)
constexpr int OFF_WST0 = 0;        // weight ring buf 0 (34816)
constexpr int OFF_WST1 = 34816;    // weight ring buf 1 (34816)
constexpr int OFF_A    = 69632;    // bf16 words 128*68 = 34816 (gating: slabs)
constexpr int OFF_B    = 104448;   // bf16 words 128*36 = 18432
constexpr int OFF_CFP  = 122880;   // float 128*66 = 33792 (gating: fga/fgb)
constexpr int OFF_CMB  = 156672;   // bf16 words 128*132 = 67584
constexpr int OFF_GW   = 224256;   // float 128*4 = 2048
constexpr int SMEM_TOTAL = 226304;
constexpr int SLAB_BYTES = 18432;
constexpr int W3_OFF   = 17408;    // W3 offset inside merged W2W3 buffer

// pitches
constexpr int P_CM = 132;  // words; 33*16B, 33%8=1 -> LDSM conflict-free
constexpr int P_A  = 68;   // 17*16B
constexpr int P_B  = 36;   // 9*16B
constexpr int P_CF = 66;   // floats
constexpr int P_SL = 36;   // slab pitch (floats)

DINL float tanh_ap(float x) {
    float y; asm("tanh.approx.f32 %0, %1;" : "=f"(y) : "f"(x)); return y;
}
DINL float sigm(float x)   { return fmaf(tanh_ap(0.5f * x), 0.5f, 0.5f); }
DINL float swishf(float x) { return x * sigm(x); }
DINL uint32_t sm_addr(const void* p) {
    return (uint32_t)__cvta_generic_to_shared(p);
}
DINL void mma16(float* d, const uint32_t* a, uint32_t b0, uint32_t b1) {
    asm volatile(
        "mma.sync.aligned.m16n8k16.row.col.f32.bf16.bf16.f32 "
        "{%0,%1,%2,%3},{%4,%5,%6,%7},{%8,%9},{%0,%1,%2,%3};"
        : "+f"(d[0]), "+f"(d[1]), "+f"(d[2]), "+f"(d[3])
        : "r"(a[0]), "r"(a[1]), "r"(a[2]), "r"(a[3]), "r"(b0), "r"(b1));
}
DINL void ldsm4(uint32_t& r0, uint32_t& r1, uint32_t& r2, uint32_t& r3,
                uint32_t addr) {
    asm volatile(
        "ldmatrix.sync.aligned.m8n8.x4.shared.b16 {%0,%1,%2,%3}, [%4];"
        : "=r"(r0), "=r"(r1), "=r"(r2), "=r"(r3) : "r"(addr));
}
DINL uint32_t packbf(float lo, float hi) {
    __nv_bfloat162 p = __floats2bfloat162_rn(lo, hi);
    return *reinterpret_cast<uint32_t*>(&p);
}
DINL float2 unpkbf(uint32_t w) {
    __nv_bfloat162 b = *reinterpret_cast<__nv_bfloat162*>(&w);
    return __bfloat1622float2(b);
}
DINL void cp16(uint32_t dst, const void* src) {
    asm volatile("cp.async.cg.shared.global [%0], [%1], 16;"
                 :: "r"(dst), "l"(src));
}
DINL void cp_commit() { asm volatile("cp.async.commit_group;" ::: "memory"); }
DINL void cp_wait0()  { asm volatile("cp.async.wait_group 0;" ::: "memory"); }

// ---- single merged prep: all W[K][N] fp32 -> bf16 W^T [N][K] images -------
__global__ void prep_all(const float* __restrict__ eW1,
                         const float* __restrict__ eW2,
                         const float* __restrict__ eW3,
                         const float* __restrict__ tgW1,
                         const float* __restrict__ twW1)
{
    const int SZ1 = 6 * 128 * 256, SZ2 = 6 * 64 * 128, SZ3 = 6 * 64 * 64;
    const int SZ4 = 4 * 64 * 256,  SZ5 = 4 * 64 * 64;
    const int total = SZ1 + SZ2 + SZ3 + SZ4 + SZ5;
    for (int gi = blockIdx.x * blockDim.x + threadIdx.x; gi < total;
         gi += gridDim.x * blockDim.x) {
        int idx = gi, dstOff, K, N;
        const float* src;
        if (idx < SZ1)                 { dstOff = IW1; src = eW1;  K = 256; N = 128; }
        else if ((idx -= SZ1) < SZ2)   { dstOff = IW2; src = eW2;  K = 128; N = 64; }
        else if ((idx -= SZ2) < SZ3)   { dstOff = IW3; src = eW3;  K = 64;  N = 64; }
        else if ((idx -= SZ3) < SZ4)   { dstOff = ITG; src = tgW1; K = 256; N = 64; }
        else         { idx -= SZ4;       dstOff = IT1; src = twW1; K = 64;  N = 64; }
        const int m   = idx / (K * N);
        const int rem = idx - m * (K * N);
        const int n   = rem / K;
        const int k   = rem - n * K;
        g_wimg[dstOff + idx] = __float2bfloat16(src[(size_t)m * K * N + k * N + n]);
    }
}

// ---- cp.async stage of one weight chunk into a ring buffer ----------------
template<int NR, int UPR, int KU, bool COMMIT = true>
DINL void stage_chunk(uint32_t dst, const __nv_bfloat16* Wimg, int kc, int tid)
{
    constexpr int P16   = UPR + 1;
    constexpr int UNITS = NR * UPR / THREADS;
    const uint4* gsrc = reinterpret_cast<const uint4*>(Wimg);
#pragma unroll
    for (int j = 0; j < UNITS; j++) {
        const int i = tid + j * THREADS;
        cp16(dst + (uint32_t)((i / UPR) * P16 + (i % UPR)) * 16,
             gsrc + (i / UPR) * KU + kc * UPR + (i % UPR));
    }
    if (COMMIT) cp_commit();
}

// ---- MMA over one staged chunk (CHK K-cols) -------------------------------
template<int N, int CHK, int AP2>
DINL void mma_chunk(float acc[][4][4], const uint32_t* As, uint32_t buf,
                    int kc, int tid)
{
    constexpr int WN  = (N >= 128) ? 4 : 2;
    constexpr int MT  = (N >= 128) ? 2 : 1;
    constexpr int P16 = CHK / 8 + 1;
    const int w = tid >> 5, lane = tid & 31;
    const int col0  = (w % WN) * 32;
    const int mrow0 = (w / WN) * (MT * 16);
    const int lrow = lane & 7, lg8 = (lane >> 3) & 1, lg16 = lane >> 4;

    const uint32_t abase = sm_addr(As);
    uint32_t a_addr[MT];
#pragma unroll
    for (int mt = 0; mt < MT; mt++)
        a_addr[mt] = abase +
            ((mrow0 + mt * 16 + lg8 * 8 + lrow) * AP2 + lg16 * 4) * 4;
    uint32_t b_addr[2];
#pragma unroll
    for (int p = 0; p < 2; p++)
        b_addr[p] = buf +
            (uint32_t)(col0 + p * 16 + lg16 * 8 + lrow) * (P16 * 16) + lg8 * 16;

#pragma unroll
    for (int ks2 = 0; ks2 < CHK / 16; ks2++) {
        const int ksg = kc * (CHK / 16) + ks2;
        uint32_t af[MT][4];
#pragma unroll
        for (int mt = 0; mt < MT; mt++)
            ldsm4(af[mt][0], af[mt][1], af[mt][2], af[mt][3],
                  a_addr[mt] + ksg * 32);
        uint32_t bf[4][2];
#pragma unroll
        for (int p = 0; p < 2; p++)
            ldsm4(bf[2 * p][0], bf[2 * p][1], bf[2 * p + 1][0], bf[2 * p + 1][1],
                  b_addr[p] + ks2 * 32);
#pragma unroll
        for (int nt = 0; nt < 4; nt++)
#pragma unroll
            for (int mt = 0; mt < MT; mt++)
                mma16(acc[mt][nt], af[mt], bf[nt][0], bf[nt][1]);
    }
}

// ---- epilogue: bias (+swish), store fp32 or packed bf16 -------------------
template<int N, bool SW, bool OUTBF, int CP>
DINL void epilogue(float acc[][4][4], const float* __restrict__ bias,
                   void* Cs, int tid)
{
    constexpr int WN = (N >= 128) ? 4 : 2;
    constexpr int MT = (N >= 128) ? 2 : 1;
    const int w = tid >> 5, lane = tid & 31;
    const int col0  = (w % WN) * 32;
    const int mrow0 = (w / WN) * (MT * 16);
    const int r = lane >> 2, c = lane & 3;
#pragma unroll
    for (int mt = 0; mt < MT; mt++) {
        const int row = mrow0 + mt * 16 + r;
#pragma unroll
        for (int nt = 0; nt < 4; nt++) {
            const int cn = col0 + nt * 8 + 2 * c;
            const float bb0 = __ldg(&bias[cn]), bb1 = __ldg(&bias[cn + 1]);
            float v0 = acc[mt][nt][0] + bb0, v1 = acc[mt][nt][1] + bb1;
            float v2 = acc[mt][nt][2] + bb0, v3 = acc[mt][nt][3] + bb1;
            if (SW) { v0 = swishf(v0); v1 = swishf(v1); v2 = swishf(v2); v3 = swishf(v3); }
            if (OUTBF) {
                uint32_t* C = reinterpret_cast<uint32_t*>(Cs);
                C[row * CP + (cn >> 1)]       = packbf(v0, v1);
                C[(row + 8) * CP + (cn >> 1)] = packbf(v2, v3);
            } else {
                float* C = reinterpret_cast<float*>(Cs);
                C[row * CP + cn] = v0; C[row * CP + cn + 1] = v1;
                C[(row + 8) * CP + cn] = v2; C[(row + 8) * CP + cn + 1] = v3;
            }
        }
    }
}

// small SIMT gemm for tower layer 2 (N=32)
DINL void gemm_t2(const float* As, const float* __restrict__ Wg,
                  const float* __restrict__ bg, float* Cs, int tid)
{
    constexpr int CT = 8, TM = 2;
    const int tc = tid % CT, tr = tid / CT;
    const int col = tc * 4;
    float acc[TM][4];
#pragma unroll
    for (int m = 0; m < TM; m++) {
        acc[m][0] = 0.f; acc[m][1] = 0.f; acc[m][2] = 0.f; acc[m][3] = 0.f;
    }
    for (int k = 0; k < 64; k++) {
        const float4 wv = __ldg(reinterpret_cast<const float4*>(Wg + (size_t)k * 32 + col));
#pragma unroll
        for (int m = 0; m < TM; m++) {
            const float a = As[(tr * TM + m) * P_CF + k];
            acc[m][0] = fmaf(a, wv.x, acc[m][0]);
            acc[m][1] = fmaf(a, wv.y, acc[m][1]);
            acc[m][2] = fmaf(a, wv.z, acc[m][2]);
            acc[m][3] = fmaf(a, wv.w, acc[m][3]);
        }
    }
    const float4 bv = __ldg(reinterpret_cast<const float4*>(bg + col));
#pragma unroll
    for (int m = 0; m < TM; m++) {
        float* cp = Cs + (tr * TM + m) * P_B + col;
        cp[0] = swishf(acc[m][0] + bv.x);
        cp[1] = swishf(acc[m][1] + bv.y);
        cp[2] = swishf(acc[m][2] + bv.z);
        cp[3] = swishf(acc[m][3] + bv.w);
    }
}

__global__ __launch_bounds__(THREADS, 1)
void home_kernel(
    const float* __restrict__ z_shared, const float* __restrict__ z_g0,
    const float* __restrict__ z_g1,
    const float* __restrict__ exp_b1, const float* __restrict__ exp_b2,
    const float* __restrict__ exp_b3,
    const float* __restrict__ ln_s,   const float* __restrict__ ln_b,
    const float* __restrict__ fg_A,   const float* __restrict__ fg_B,
    const float* __restrict__ tg_b1,
    const float* __restrict__ tg_W2,  const float* __restrict__ tg_b2,
    const float* __restrict__ sg_W,   const float* __restrict__ sg_b,
    const float* __restrict__ tw_b1,
    const float* __restrict__ tw_W2,  const float* __restrict__ tw_b2,
    const float* __restrict__ tw_W3,  const float* __restrict__ tw_b3,
    float* __restrict__ out)
{
    extern __shared__ char sm[];
    float*    fga   = reinterpret_cast<float*>(sm + OFF_CFP);          // [256][8]
    float*    fgb   = reinterpret_cast<float*>(sm + OFF_CFP + 8192);   // [8][256]
    float*    slab0 = reinterpret_cast<float*>(sm + OFF_A);
    float*    slab1 = reinterpret_cast<float*>(sm + OFF_A + SLAB_BYTES);
    uint32_t* cmw   = reinterpret_cast<uint32_t*>(sm + OFF_CMB);
    uint32_t* aw    = reinterpret_cast<uint32_t*>(sm + OFF_A);
    uint32_t* bw    = reinterpret_cast<uint32_t*>(sm + OFF_B);
    float*    cfp   = reinterpret_cast<float*>(sm + OFF_CFP);
    float*    gwb   = reinterpret_cast<float*>(sm + OFF_GW);
    float*    lgb   = reinterpret_cast<float*>(sm + OFF_B);
    float*    twh2  = reinterpret_cast<float*>(sm + OFF_B);

    const uint32_t wstA[2] = { sm_addr(sm + OFF_WST0), sm_addr(sm + OFF_WST1) };

    const int tid  = threadIdx.x;
    const int wid  = tid >> 5, lane = tid & 31;
    const int t    = blockIdx.y;
    const int g    = t >> 1;                    // TASK_TO_GROUP = {0,0,1,1}
    const int row0 = blockIdx.x * ROWS;
    const float* zg = g ? z_g1 : z_g0;

    // ---- prefetch TG weights into buf0 (overlaps all of gating) ----------
    stage_chunk<64, 32, 32>(wstA[0], g_wimg + ITG + t * 16384, 0, tid);

    // ---- stage fgA [256][8], fgB [8][256] into smem ----------------------
    {
        const float4* A4 = reinterpret_cast<const float4*>(fg_A + (size_t)t * 2048);
        const float4* B4 = reinterpret_cast<const float4*>(fg_B + (size_t)t * 2048);
        reinterpret_cast<float4*>(fga)[tid] = __ldg(&A4[tid]);
        reinterpret_cast<float4*>(fgb)[tid] = __ldg(&B4[tid]);
    }

    // ---- pass 1: double-buffered slab; racc = cm @ fgA; pack UNGATED cm --
    const int grow = tid >> 2;            // 0..127 (row)
    const int jp   = (tid & 3) * 2;       // 0,2,4,6
    float r0 = 0.f, r1 = 0.f;
#pragma unroll
    for (int j = 0; j < 2; j++) {
        const int i = tid + j * THREADS;
        *reinterpret_cast<float4*>(&slab0[(i >> 3) * P_SL + (i & 7) * 4]) =
            *reinterpret_cast<const float4*>(
                z_shared + (size_t)(row0 + (i >> 3)) * META + (i & 7) * 4);
    }
#pragma unroll 1
    for (int ch = 0; ch < 8; ch++) {
        __syncthreads();
        const float* cur = (ch & 1) ? slab1 : slab0;
        float4 zr[2];
        const bool more = (ch < 7);
        if (more) {
            const float* zsrc = (ch + 1 < 4) ? z_shared : zg;
            const int cb = ((ch + 1) & 3) * 32;
#pragma unroll
            for (int j = 0; j < 2; j++) {
                const int i = tid + j * THREADS;
                zr[j] = *reinterpret_cast<const float4*>(
                    zsrc + (size_t)(row0 + (i >> 3)) * META + cb + (i & 7) * 4);
            }
        }
#pragma unroll 8
        for (int k = 0; k < 32; k++) {
            const float a = cur[grow * P_SL + k];
            const float2 f = *reinterpret_cast<const float2*>(
                &fga[(ch * 32 + k) * 8 + jp]);
            r0 = fmaf(a, f.x, r0);
            r1 = fmaf(a, f.y, r1);
        }
#pragma unroll
        for (int i2 = 0; i2 < 4; i2++) {
            const int p = tid + i2 * THREADS;
            const int row = p >> 4, pp = p & 15;
            const float2 v = *reinterpret_cast<const float2*>(
                &cur[row * P_SL + 2 * pp]);
            cmw[row * P_CM + ch * 16 + pp] = packbf(v.x, v.y);
        }
        if (more) {
            float* nxt = (ch & 1) ? slab0 : slab1;
#pragma unroll
            for (int j = 0; j < 2; j++) {
                const int i = tid + j * THREADS;
                *reinterpret_cast<float4*>(&nxt[(i >> 3) * P_SL + (i & 7) * 4]) = zr[j];
            }
        }
    }
    // assemble full r[8] per thread via shuffles (4 threads share a row)
    float rr[8];
    {
        const int lb = lane & ~3;
#pragma unroll
        for (int k2 = 0; k2 < 4; k2++) {
            rr[2 * k2]     = __shfl_sync(0xffffffffu, r0, lb + k2);
            rr[2 * k2 + 1] = __shfl_sync(0xffffffffu, r1, lb + k2);
        }
    }
    __syncthreads();   // cmw pass-1 writes -> pass-2 reads

    // ---- pass 2: gate cmw in place, vectorized (thread = 64 cols of row) --
    {
        uint32_t* cmrow = cmw + grow * P_CM;
        const int cb4 = (tid & 3) * 8;     // uint4 index base (8 uint4 = 64 cols)
#pragma unroll
        for (int u = 0; u < 8; u++) {
            const int i4 = cb4 + u;
            uint4 w4 = *reinterpret_cast<uint4*>(cmrow + i4 * 4);
            const float2 v0 = unpkbf(w4.x), v1 = unpkbf(w4.y);
            const float2 v2 = unpkbf(w4.z), v3 = unpkbf(w4.w);
            float d[8];
#pragma unroll
            for (int q = 0; q < 8; q++) d[q] = 0.f;
#pragma unroll
            for (int j = 0; j < 8; j++) {
                const float rj = rr[j];
                const float4 f0 = *reinterpret_cast<const float4*>(&fgb[j * 256 + i4 * 8]);
                const float4 f1 = *reinterpret_cast<const float4*>(&fgb[j * 256 + i4 * 8 + 4]);
                d[0] = fmaf(rj, f0.x, d[0]); d[1] = fmaf(rj, f0.y, d[1]);
                d[2] = fmaf(rj, f0.z, d[2]); d[3] = fmaf(rj, f0.w, d[3]);
                d[4] = fmaf(rj, f1.x, d[4]); d[5] = fmaf(rj, f1.y, d[5]);
                d[6] = fmaf(rj, f1.z, d[6]); d[7] = fmaf(rj, f1.w, d[7]);
            }
            uint4 o;
            o.x = packbf(v0.x * 2.0f * sigm(d[0]), v0.y * 2.0f * sigm(d[1]));
            o.y = packbf(v1.x * 2.0f * sigm(d[2]), v1.y * 2.0f * sigm(d[3]));
            o.z = packbf(v2.x * 2.0f * sigm(d[4]), v2.y * 2.0f * sigm(d[5]));
            o.w = packbf(v3.x * 2.0f * sigm(d[6]), v3.y * 2.0f * sigm(d[7]));
            *reinterpret_cast<uint4*>(cmrow + i4 * 4) = o;
        }
    }

    // ---- task gate GEMM (buf0), prefetch W1[e0]c0 into buf1 ---------------
    cp_wait0();
    __syncthreads();   // TG staged + cmw gated, visible to all
    stage_chunk<128, 16, 32>(wstA[1], g_wimg + IW1 + 0 * 32768, 0, tid);
    {
        float acc[1][4][4];
#pragma unroll
        for (int nt = 0; nt < 4; nt++)
#pragma unroll
            for (int i = 0; i < 4; i++) acc[0][nt][i] = 0.f;
        mma_chunk<64, 256, P_CM>(acc, cmw, wstA[0], 0, tid);
        epilogue<64, true, false, P_CF>(acc, tg_b1 + t * 64, cfp, tid);
    }
    __syncthreads();
    {
        const int row = tid >> 2, j = tid & 3;
        const float* W = tg_W2 + (size_t)t * 64 * 4;
        float acc = __ldg(&tg_b2[t * 4 + j]);
#pragma unroll 4
        for (int c2 = 0; c2 < 64; c2++)
            acc = fmaf(cfp[row * P_CF + c2], __ldg(&W[c2 * 4 + j]), acc);
        lgb[row * 4 + j] = acc;
    }
    __syncthreads();
    if (tid < ROWS) {
        const float l0 = lgb[tid * 4 + 0], l1 = lgb[tid * 4 + 1];
        const float l2 = lgb[tid * 4 + 2], l3 = lgb[tid * 4 + 3];
        const float m  = fmaxf(fmaxf(l0, l1), fmaxf(l2, l3));
        const float e0f = __expf(l0 - m), e1f = __expf(l1 - m);
        const float e2f = __expf(l2 - m), e3f = __expf(l3 - m);
        const float inv = 1.0f / (e0f + e1f + e2f + e3f);
        gwb[tid * 4 + 0] = e0f * inv; gwb[tid * 4 + 1] = e1f * inv;
        gwb[tid * 4 + 2] = e2f * inv; gwb[tid * 4 + 3] = e3f * inv;
    }
    // next step's barrier publishes gwb before any reader

    // ---- expert loop: 3-step ring per expert ------------------------------
    // trace: TG(buf0) -> e: W1c0(1), W1c1(0), W2W3(1) -> e+1: W1c0(0), ...
    int cur = 1;
    float ag0[8], ag1[8];
#pragma unroll 1
    for (int ep = 0; ep < 4; ep++) {
        const int e = (ep < 2) ? ep : (ep + 2 * g);

        // ---- W1: two 128-K chunks ----
        float acc1[2][4][4];
#pragma unroll
        for (int mt = 0; mt < 2; mt++)
#pragma unroll
            for (int nt = 0; nt < 4; nt++)
#pragma unroll
                for (int i = 0; i < 4; i++) acc1[mt][nt][i] = 0.f;

        cp_wait0(); __syncthreads();
        stage_chunk<128, 16, 32>(wstA[cur ^ 1], g_wimg + IW1 + e * 32768, 1, tid);
        mma_chunk<128, 128, P_CM>(acc1, cmw, wstA[cur], 0, tid);
        cur ^= 1;

        cp_wait0(); __syncthreads();
        // merged stage: W2 at offset 0, W3 at offset W3_OFF, one commit
        stage_chunk<64, 16, 16, false>(wstA[cur ^ 1],
                                       g_wimg + IW2 + e * 8192, 0, tid);
        stage_chunk<64, 8, 8, true>(wstA[cur ^ 1] + W3_OFF,
                                    g_wimg + IW3 + e * 4096, 0, tid);
        mma_chunk<128, 128, P_CM>(acc1, cmw, wstA[cur], 1, tid);
        cur ^= 1;
        epilogue<128, true, true, P_A>(acc1, exp_b1 + e * 128, aw, tid);

        // ---- W2 + W3 (single staged buffer) ----
        float acc2[1][4][4];
#pragma unroll
        for (int nt = 0; nt < 4; nt++)
#pragma unroll
            for (int i = 0; i < 4; i++) acc2[0][nt][i] = 0.f;
        cp_wait0(); __syncthreads();   // W2W3 ready + aw published
        if (ep < 3) {
            const int en = (ep + 1 < 2) ? (ep + 1) : (ep + 1 + 2 * g);
            stage_chunk<128, 16, 32>(wstA[cur ^ 1], g_wimg + IW1 + en * 32768, 0, tid);
        } else {
            stage_chunk<64, 8, 8>(wstA[cur ^ 1], g_wimg + IT1 + t * 4096, 0, tid);
        }
        mma_chunk<64, 128, P_A>(acc2, aw, wstA[cur], 0, tid);
        epilogue<64, true, true, P_B>(acc2, exp_b2 + e * 64, bw, tid);
        __syncthreads();               // publish bw for W3 MMA

        float acc3[1][4][4];
#pragma unroll
        for (int nt = 0; nt < 4; nt++)
#pragma unroll
            for (int i = 0; i < 4; i++) acc3[0][nt][i] = 0.f;
        mma_chunk<64, 64, P_B>(acc3, bw, wstA[cur] + W3_OFF, 0, tid);
        cur ^= 1;
        epilogue<64, false, false, P_CF>(acc3, exp_b3 + e * 64, cfp, tid);
        __syncthreads();               // publish cfp for LN

        // ---- LN + diag self-gate + softmax aggregation ----
        {
            const float* lS  = ln_s + e * 64;
            const float* lB  = ln_b + e * 64;
            const float* sgw = sg_W + (size_t)t * 256;
            const float  sgb = __ldg(&sg_b[t * 4 + ep]);
            const int c0 = 2 * lane, c1 = 2 * lane + 1;
#pragma unroll
            for (int rr2 = 0; rr2 < 8; rr2++) {
                const int row = wid * 8 + rr2;
                const float2 v = *reinterpret_cast<const float2*>(&cfp[row * P_CF + c0]);
                float sum = v.x + v.y;
                float sq  = fmaf(v.x, v.x, v.y * v.y);
#pragma unroll
                for (int o = 16; o; o >>= 1) {
                    sum += __shfl_xor_sync(0xffffffffu, sum, o);
                    sq  += __shfl_xor_sync(0xffffffffu, sq,  o);
                }
                const float mu  = sum * (1.0f / 64.0f);
                const float var = sq * (1.0f / 64.0f) - mu * mu;
                const float inv = rsqrtf(var + 1e-5f);
                const float n0  = fmaf((v.x - mu) * inv, __ldg(&lS[c0]), __ldg(&lB[c0]));
                const float n1  = fmaf((v.y - mu) * inv, __ldg(&lS[c1]), __ldg(&lB[c1]));
                float swp = fmaf(n0, __ldg(&sgw[c0 * 4 + ep]),
                                 n1 * __ldg(&sgw[c1 * 4 + ep]));
#pragma unroll
                for (int o = 16; o; o >>= 1)
                    swp += __shfl_xor_sync(0xffffffffu, swp, o);
                const float scale = (swp + sgb) * gwb[row * 4 + ep];
                if (ep == 0) { ag0[rr2] = n0 * scale;                ag1[rr2] = n1 * scale; }
                else         { ag0[rr2] = fmaf(n0, scale, ag0[rr2]); ag1[rr2] = fmaf(n1, scale, ag1[rr2]); }
            }
        }
        // next step's barrier orders everything
    }

    // ---- agg -> bf16 bw ----------------------------------------------------
#pragma unroll
    for (int rr2 = 0; rr2 < 8; rr2++) {
        const int row = wid * 8 + rr2;
        bw[row * P_B + lane] = packbf(ag0[rr2], ag1[rr2]);
    }

    // ---- tower layer 1 (T1 chunk already in flight) -------------------------
    {
        float accT[1][4][4];
#pragma unroll
        for (int nt = 0; nt < 4; nt++)
#pragma unroll
            for (int i = 0; i < 4; i++) accT[0][nt][i] = 0.f;
        cp_wait0(); __syncthreads();   // T1 staged + bw published
        mma_chunk<64, 64, P_B>(accT, bw, wstA[cur], 0, tid);
        epilogue<64, true, false, P_CF>(accT, tw_b1 + t * 64, cfp, tid);
    }
    __syncthreads();
    gemm_t2(cfp, tw_W2 + (size_t)t * 64 * 32, tw_b2 + t * 32, twh2, tid);
    __syncthreads();
    if (tid < ROWS) {
        const float* th = &twh2[tid * P_B];
        const float* W  = tw_W3 + t * 32;
        float acc = __ldg(&tw_b3[t]);
#pragma unroll 4
        for (int c2 = 0; c2 < 32; c2++)
            acc = fmaf(th[c2], __ldg(&W[c2]), acc);
        out[(size_t)(row0 + tid) * 4 + t] = sigm(acc);
    }
}

extern "C" void kernel_launch(void* const* d_in, const int* in_sizes, int n_in,
                              void* d_out, int out_size)
{
    (void)n_in; (void)out_size;
    const float* zs   = (const float*)d_in[0];
    const float* z0   = (const float*)d_in[1];
    const float* z1   = (const float*)d_in[2];
    const float* eW1  = (const float*)d_in[4];
    const float* eb1  = (const float*)d_in[5];
    const float* eW2  = (const float*)d_in[6];
    const float* eb2  = (const float*)d_in[7];
    const float* eW3  = (const float*)d_in[8];
    const float* eb3  = (const float*)d_in[9];
    const float* lns  = (const float*)d_in[10];
    const float* lnb  = (const float*)d_in[11];
    const float* fgA  = (const float*)d_in[12];
    const float* fgB  = (const float*)d_in[13];
    const float* tgW1 = (const float*)d_in[14];
    const float* tgb1 = (const float*)d_in[15];
    const float* tgW2 = (const float*)d_in[16];
    const float* tgb2 = (const float*)d_in[17];
    const float* sgW  = (const float*)d_in[18];
    const float* sgb  = (const float*)d_in[19];
    const float* twW1 = (const float*)d_in[20];
    const float* twb1 = (const float*)d_in[21];
    const float* twW2 = (const float*)d_in[22];
    const float* twb2 = (const float*)d_in[23];
    const float* twW3 = (const float*)d_in[24];
    const float* twb3 = (const float*)d_in[25];

    const int Bn = in_sizes[0] / META;

    prep_all<<<296, 256>>>(eW1, eW2, eW3, tgW1, twW1);

    cudaFuncSetAttribute(home_kernel, cudaFuncAttributeMaxDynamicSharedMemorySize,
                         SMEM_TOTAL);
    dim3 grid(Bn / ROWS, 4);
    home_kernel<<<grid, THREADS, SMEM_TOTAL>>>(
        zs, z0, z1, eb1, eb2, eb3, lns, lnb, fgA, fgB,
        tgb1, tgW2, tgb2, sgW, sgb, twb1, twW2, twb2, twW3, twb3,
        (float*)d_out);
}

// round 14
// speedup vs baseline: 1.6511x; 1.4638x over previous
#include <cuda_runtime.h>
#include <cuda_bf16.h>
#include <cstdint>
#include <cstddef>

#define DINL __device__ __forceinline__

// ---------------------------------------------------------------------------
// HoMESecondLayer v14: R13 + tensorized gating (r-gemm and gate-gemm on MMA),
// direct z->cmw bf16 packing, early W1c0 prefetch. ROWS=128/512thr/1 CTA/SM.
// ---------------------------------------------------------------------------

constexpr int ROWS    = 128;
constexpr int THREADS = 512;
constexpr int META    = 128;
constexpr int GIN     = 256;

// bf16 weight images in device memory
constexpr int IW1 = 0;                    // 6 x [128][256]
constexpr int IW2 = IW1 + 6 * 128 * 256;  // 6 x [64][128]
constexpr int IW3 = IW2 + 6 * 64 * 128;   // 6 x [64][64]
constexpr int ITG = IW3 + 6 * 64 * 64;    // 4 x [64][256]
constexpr int IT1 = ITG + 4 * 64 * 256;   // 4 x [64][64]
constexpr int IA8 = IT1 + 4 * 64 * 64;    // 4 x [8][256]   fgA^T
constexpr int IB8 = IA8 + 4 * 8 * 256;    // 4 x [256][8]   fgB^T
constexpr int ITOT = IB8 + 4 * 256 * 8;
__device__ __align__(16) __nv_bfloat16 g_wimg[ITOT];

// smem layout (byte offsets)
constexpr int OFF_WST0 = 0;        // weight ring buf 0 (34816)
constexpr int OFF_WST1 = 34816;    // weight ring buf 1 (34816)
constexpr int OFF_A    = 69632;    // aw region (34816); gating: fgA/fgB/rpad
constexpr int OFF_B    = 104448;   // bw 18432 (also lgb/twh2)
constexpr int OFF_CFP  = 122880;   // cfp 33792 (gating: rl/rh partials)
constexpr int OFF_CMB  = 156672;   // cmw 67584
constexpr int OFF_GW   = 224256;   // gwb 2048
constexpr int SMEM_TOTAL = 226304;
constexpr int W3_OFF   = 17408;    // W3 offset inside merged W2W3 buffer
// gating overlays
constexpr int GA_OFF = 0;          // in aw region: fgA img [8][33 u4] = 4224
constexpr int GB_OFF = 4224;       // fgB img [256][3 u4] = 12288
constexpr int RP_OFF = 16512;      // rpad [128][5 u4] = 10240
constexpr int RL_OFF = 0;          // in cfp region: [128][9] f32 = 4608
constexpr int RH_OFF = 4608;       // [128][9] f32 = 4608

// pitches
constexpr int P_CM = 132;  // words; 33*16B -> LDSM conflict-free
constexpr int P_A  = 68;
constexpr int P_B  = 36;
constexpr int P_CF = 66;

DINL float tanh_ap(float x) {
    float y; asm("tanh.approx.f32 %0, %1;" : "=f"(y) : "f"(x)); return y;
}
DINL float sigm(float x)   { return fmaf(tanh_ap(0.5f * x), 0.5f, 0.5f); }
DINL float swishf(float x) { return x * sigm(x); }
DINL uint32_t sm_addr(const void* p) {
    return (uint32_t)__cvta_generic_to_shared(p);
}
DINL void mma16(float* d, const uint32_t* a, uint32_t b0, uint32_t b1) {
    asm volatile(
        "mma.sync.aligned.m16n8k16.row.col.f32.bf16.bf16.f32 "
        "{%0,%1,%2,%3},{%4,%5,%6,%7},{%8,%9},{%0,%1,%2,%3};"
        : "+f"(d[0]), "+f"(d[1]), "+f"(d[2]), "+f"(d[3])
        : "r"(a[0]), "r"(a[1]), "r"(a[2]), "r"(a[3]), "r"(b0), "r"(b1));
}
DINL void ldsm4(uint32_t& r0, uint32_t& r1, uint32_t& r2, uint32_t& r3,
                uint32_t addr) {
    asm volatile(
        "ldmatrix.sync.aligned.m8n8.x4.shared.b16 {%0,%1,%2,%3}, [%4];"
        : "=r"(r0), "=r"(r1), "=r"(r2), "=r"(r3) : "r"(addr));
}
DINL void ldsm2(uint32_t& r0, uint32_t& r1, uint32_t addr) {
    asm volatile(
        "ldmatrix.sync.aligned.m8n8.x2.shared.b16 {%0,%1}, [%2];"
        : "=r"(r0), "=r"(r1) : "r"(addr));
}
DINL uint32_t packbf(float lo, float hi) {
    __nv_bfloat162 p = __floats2bfloat162_rn(lo, hi);
    return *reinterpret_cast<uint32_t*>(&p);
}
DINL float2 unpkbf(uint32_t w) {
    __nv_bfloat162 b = *reinterpret_cast<__nv_bfloat162*>(&w);
    return __bfloat1622float2(b);
}
DINL void cp16(uint32_t dst, const void* src) {
    asm volatile("cp.async.cg.shared.global [%0], [%1], 16;"
                 :: "r"(dst), "l"(src));
}
DINL void cp_commit() { asm volatile("cp.async.commit_group;" ::: "memory"); }
DINL void cp_wait0()  { asm volatile("cp.async.wait_group 0;" ::: "memory"); }
DINL void cp_wait1()  { asm volatile("cp.async.wait_group 1;" ::: "memory"); }

// ---- merged prep: all W[K][N] fp32 -> bf16 W^T [N][K] images --------------
__global__ void prep_all(const float* __restrict__ eW1,
                         const float* __restrict__ eW2,
                         const float* __restrict__ eW3,
                         const float* __restrict__ tgW1,
                         const float* __restrict__ twW1,
                         const float* __restrict__ fgA,
                         const float* __restrict__ fgB)
{
    const int SZ1 = 6 * 128 * 256, SZ2 = 6 * 64 * 128, SZ3 = 6 * 64 * 64;
    const int SZ4 = 4 * 64 * 256,  SZ5 = 4 * 64 * 64;
    const int SZ6 = 4 * 8 * 256,   SZ7 = 4 * 256 * 8;
    const int total = SZ1 + SZ2 + SZ3 + SZ4 + SZ5 + SZ6 + SZ7;
    for (int gi = blockIdx.x * blockDim.x + threadIdx.x; gi < total;
         gi += gridDim.x * blockDim.x) {
        int idx = gi, dstOff, K, N;
        const float* src;
        if (idx < SZ1)                 { dstOff = IW1; src = eW1;  K = 256; N = 128; }
        else if ((idx -= SZ1) < SZ2)   { dstOff = IW2; src = eW2;  K = 128; N = 64; }
        else if ((idx -= SZ2) < SZ3)   { dstOff = IW3; src = eW3;  K = 64;  N = 64; }
        else if ((idx -= SZ3) < SZ4)   { dstOff = ITG; src = tgW1; K = 256; N = 64; }
        else if ((idx -= SZ4) < SZ5)   { dstOff = IT1; src = twW1; K = 64;  N = 64; }
        else if ((idx -= SZ5) < SZ6)   { dstOff = IA8; src = fgA;  K = 256; N = 8; }
        else         { idx -= SZ6;       dstOff = IB8; src = fgB;  K = 8;   N = 256; }
        const int m   = idx / (K * N);
        const int rem = idx - m * (K * N);
        const int n   = rem / K;
        const int k   = rem - n * K;
        g_wimg[dstOff + idx] = __float2bfloat16(src[(size_t)m * K * N + k * N + n]);
    }
}

// ---- cp.async stage of one weight chunk into a ring buffer ----------------
template<int NR, int UPR, int KU, bool COMMIT = true>
DINL void stage_chunk(uint32_t dst, const __nv_bfloat16* Wimg, int kc, int tid)
{
    constexpr int P16   = UPR + 1;
    constexpr int UNITS = NR * UPR / THREADS;
    const uint4* gsrc = reinterpret_cast<const uint4*>(Wimg);
#pragma unroll
    for (int j = 0; j < UNITS; j++) {
        const int i = tid + j * THREADS;
        cp16(dst + (uint32_t)((i / UPR) * P16 + (i % UPR)) * 16,
             gsrc + (i / UPR) * KU + kc * UPR + (i % UPR));
    }
    if (COMMIT) cp_commit();
}

// ---- MMA over one staged chunk (CHK K-cols) -------------------------------
template<int N, int CHK, int AP2>
DINL void mma_chunk(float acc[][4][4], const uint32_t* As, uint32_t buf,
                    int kc, int tid)
{
    constexpr int WN  = (N >= 128) ? 4 : 2;
    constexpr int MT  = (N >= 128) ? 2 : 1;
    constexpr int P16 = CHK / 8 + 1;
    const int w = tid >> 5, lane = tid & 31;
    const int col0  = (w % WN) * 32;
    const int mrow0 = (w / WN) * (MT * 16);
    const int lrow = lane & 7, lg8 = (lane >> 3) & 1, lg16 = lane >> 4;

    const uint32_t abase = sm_addr(As);
    uint32_t a_addr[MT];
#pragma unroll
    for (int mt = 0; mt < MT; mt++)
        a_addr[mt] = abase +
            ((mrow0 + mt * 16 + lg8 * 8 + lrow) * AP2 + lg16 * 4) * 4;
    uint32_t b_addr[2];
#pragma unroll
    for (int p = 0; p < 2; p++)
        b_addr[p] = buf +
            (uint32_t)(col0 + p * 16 + lg16 * 8 + lrow) * (P16 * 16) + lg8 * 16;

#pragma unroll
    for (int ks2 = 0; ks2 < CHK / 16; ks2++) {
        const int ksg = kc * (CHK / 16) + ks2;
        uint32_t af[MT][4];
#pragma unroll
        for (int mt = 0; mt < MT; mt++)
            ldsm4(af[mt][0], af[mt][1], af[mt][2], af[mt][3],
                  a_addr[mt] + ksg * 32);
        uint32_t bf[4][2];
#pragma unroll
        for (int p = 0; p < 2; p++)
            ldsm4(bf[2 * p][0], bf[2 * p][1], bf[2 * p + 1][0], bf[2 * p + 1][1],
                  b_addr[p] + ks2 * 32);
#pragma unroll
        for (int nt = 0; nt < 4; nt++)
#pragma unroll
            for (int mt = 0; mt < MT; mt++)
                mma16(acc[mt][nt], af[mt], bf[nt][0], bf[nt][1]);
    }
}

// ---- epilogue: bias (+swish), store fp32 or packed bf16 -------------------
template<int N, bool SW, bool OUTBF, int CP>
DINL void epilogue(float acc[][4][4], const float* __restrict__ bias,
                   void* Cs, int tid)
{
    constexpr int WN = (N >= 128) ? 4 : 2;
    constexpr int MT = (N >= 128) ? 2 : 1;
    const int w = tid >> 5, lane = tid & 31;
    const int col0  = (w % WN) * 32;
    const int mrow0 = (w / WN) * (MT * 16);
    const int r = lane >> 2, c = lane & 3;
#pragma unroll
    for (int mt = 0; mt < MT; mt++) {
        const int row = mrow0 + mt * 16 + r;
#pragma unroll
        for (int nt = 0; nt < 4; nt++) {
            const int cn = col0 + nt * 8 + 2 * c;
            const float bb0 = __ldg(&bias[cn]), bb1 = __ldg(&bias[cn + 1]);
            float v0 = acc[mt][nt][0] + bb0, v1 = acc[mt][nt][1] + bb1;
            float v2 = acc[mt][nt][2] + bb0, v3 = acc[mt][nt][3] + bb1;
            if (SW) { v0 = swishf(v0); v1 = swishf(v1); v2 = swishf(v2); v3 = swishf(v3); }
            if (OUTBF) {
                uint32_t* C = reinterpret_cast<uint32_t*>(Cs);
                C[row * CP + (cn >> 1)]       = packbf(v0, v1);
                C[(row + 8) * CP + (cn >> 1)] = packbf(v2, v3);
            } else {
                float* C = reinterpret_cast<float*>(Cs);
                C[row * CP + cn] = v0; C[row * CP + cn + 1] = v1;
                C[(row + 8) * CP + cn] = v2; C[(row + 8) * CP + cn + 1] = v3;
            }
        }
    }
}

// small SIMT gemm for tower layer 2 (N=32)
DINL void gemm_t2(const float* As, const float* __restrict__ Wg,
                  const float* __restrict__ bg, float* Cs, int tid)
{
    constexpr int CT = 8, TM = 2;
    const int tc = tid % CT, tr = tid / CT;
    const int col = tc * 4;
    float acc[TM][4];
#pragma unroll
    for (int m = 0; m < TM; m++) {
        acc[m][0] = 0.f; acc[m][1] = 0.f; acc[m][2] = 0.f; acc[m][3] = 0.f;
    }
    for (int k = 0; k < 64; k++) {
        const float4 wv = __ldg(reinterpret_cast<const float4*>(Wg + (size_t)k * 32 + col));
#pragma unroll
        for (int m = 0; m < TM; m++) {
            const float a = As[(tr * TM + m) * P_CF + k];
            acc[m][0] = fmaf(a, wv.x, acc[m][0]);
            acc[m][1] = fmaf(a, wv.y, acc[m][1]);
            acc[m][2] = fmaf(a, wv.z, acc[m][2]);
            acc[m][3] = fmaf(a, wv.w, acc[m][3]);
        }
    }
    const float4 bv = __ldg(reinterpret_cast<const float4*>(bg + col));
#pragma unroll
    for (int m = 0; m < TM; m++) {
        float* cp = Cs + (tr * TM + m) * P_B + col;
        cp[0] = swishf(acc[m][0] + bv.x);
        cp[1] = swishf(acc[m][1] + bv.y);
        cp[2] = swishf(acc[m][2] + bv.z);
        cp[3] = swishf(acc[m][3] + bv.w);
    }
}

__global__ __launch_bounds__(THREADS, 1)
void home_kernel(
    const float* __restrict__ z_shared, const float* __restrict__ z_g0,
    const float* __restrict__ z_g1,
    const float* __restrict__ exp_b1, const float* __restrict__ exp_b2,
    const float* __restrict__ exp_b3,
    const float* __restrict__ ln_s,   const float* __restrict__ ln_b,
    const float* __restrict__ tg_b1,
    const float* __restrict__ tg_W2,  const float* __restrict__ tg_b2,
    const float* __restrict__ sg_W,   const float* __restrict__ sg_b,
    const float* __restrict__ tw_b1,
    const float* __restrict__ tw_W2,  const float* __restrict__ tw_b2,
    const float* __restrict__ tw_W3,  const float* __restrict__ tw_b3,
    float* __restrict__ out)
{
    extern __shared__ char sm[];
    uint32_t* cmw  = reinterpret_cast<uint32_t*>(sm + OFF_CMB);
    uint32_t* aw   = reinterpret_cast<uint32_t*>(sm + OFF_A);
    uint32_t* bw   = reinterpret_cast<uint32_t*>(sm + OFF_B);
    float*    cfp  = reinterpret_cast<float*>(sm + OFF_CFP);
    float*    gwb  = reinterpret_cast<float*>(sm + OFF_GW);
    float*    lgb  = reinterpret_cast<float*>(sm + OFF_B);
    float*    twh2 = reinterpret_cast<float*>(sm + OFF_B);
    float*    rl   = reinterpret_cast<float*>(sm + OFF_CFP + RL_OFF);
    float*    rh   = reinterpret_cast<float*>(sm + OFF_CFP + RH_OFF);

    const uint32_t wstA[2] = { sm_addr(sm + OFF_WST0), sm_addr(sm + OFF_WST1) };
    const uint32_t fgAsm = sm_addr(sm + OFF_A + GA_OFF);
    const uint32_t fgBsm = sm_addr(sm + OFF_A + GB_OFF);
    const uint32_t rpsm  = sm_addr(sm + OFF_A + RP_OFF);
    const uint32_t cmbase = sm_addr(cmw);

    const int tid  = threadIdx.x;
    const int wid  = tid >> 5, lane = tid & 31;
    const int t    = blockIdx.y;
    const int g    = t >> 1;                    // TASK_TO_GROUP = {0,0,1,1}
    const int row0 = blockIdx.x * ROWS;
    const float* zg = g ? z_g1 : z_g0;

    // ---- prefetch TG -> buf0 and W1[0]c0 -> buf1 (overlap all gating) ----
    stage_chunk<64, 32, 32>(wstA[0], g_wimg + ITG + t * 16384, 0, tid);
    stage_chunk<128, 16, 32>(wstA[1], g_wimg + IW1, 0, tid);

    // ---- stage fgA/fgB bf16 images into smem (LDG+STS, small) ------------
    {
        const uint4* a8 = reinterpret_cast<const uint4*>(g_wimg + IA8 + t * 2048);
        uint4* da = reinterpret_cast<uint4*>(sm + OFF_A + GA_OFF);
        if (tid < 256) {
            const int row = tid >> 5, u = tid & 31;
            da[row * 33 + u] = __ldg(&a8[row * 32 + u]);
        }
        const uint4* b8 = reinterpret_cast<const uint4*>(g_wimg + IB8 + t * 2048);
        uint4* db = reinterpret_cast<uint4*>(sm + OFF_A + GB_OFF);
        const int row = tid >> 1, h = tid & 1;
        db[row * 3 + h] = h ? make_uint4(0, 0, 0, 0) : __ldg(&b8[row]);
    }

    // ---- z -> ungated bf16 cmw (direct, coalesced) ------------------------
#pragma unroll
    for (int j = 0; j < 16; j++) {
        const int idx = tid + j * THREADS;
        const int row = idx >> 6, fc = idx & 63;
        const float4 v = (fc < 32)
            ? *reinterpret_cast<const float4*>(z_shared + (size_t)(row0 + row) * META + fc * 4)
            : *reinterpret_cast<const float4*>(zg + (size_t)(row0 + row) * META + (fc - 32) * 4);
        uint2 o;
        o.x = packbf(v.x, v.y);
        o.y = packbf(v.z, v.w);
        *reinterpret_cast<uint2*>(&cmw[row * P_CM + fc * 2]) = o;
    }
    __syncthreads();

    // ---- r-gemm: r[128][8] = cm @ fgA, K split over warp halves -----------
    {
        const int kh    = wid >> 3;           // 0: k 0-127, 1: k 128-255
        const int mrow0 = (wid & 7) * 16;
        const int lrow = lane & 7, lg8 = (lane >> 3) & 1, lg16 = lane >> 4;
        const uint32_t a0 = cmbase + ((mrow0 + lg8 * 8 + lrow) * P_CM + lg16 * 4) * 4;
        const int l2 = lane & 15;
        const uint32_t b0a = fgAsm + (uint32_t)(l2 & 7) * 528 + (l2 >> 3) * 16;
        float acc[4] = {0.f, 0.f, 0.f, 0.f};
#pragma unroll
        for (int ks = 0; ks < 8; ks++) {
            const int ksg = kh * 8 + ks;
            uint32_t af[4];
            ldsm4(af[0], af[1], af[2], af[3], a0 + ksg * 32);
            uint32_t b0, b1;
            ldsm2(b0, b1, b0a + ksg * 32);
            mma16(acc, af, b0, b1);
        }
        const int r = lane >> 2, c = lane & 3;
        float* dst = kh ? rh : rl;
        dst[(mrow0 + r) * 9 + 2 * c]     = acc[0];
        dst[(mrow0 + r) * 9 + 2 * c + 1] = acc[1];
        dst[(mrow0 + r + 8) * 9 + 2 * c]     = acc[2];
        dst[(mrow0 + r + 8) * 9 + 2 * c + 1] = acc[3];
    }
    __syncthreads();

    // ---- combine partials -> rpad [128][K=16 bf16, pitch 5 u4] ------------
    {
        uint32_t* rp = reinterpret_cast<uint32_t*>(sm + OFF_A + RP_OFF);
        const int row = tid >> 2, cp2 = (tid & 3) * 2;
        const float v0 = rl[row * 9 + cp2]     + rh[row * 9 + cp2];
        const float v1 = rl[row * 9 + cp2 + 1] + rh[row * 9 + cp2 + 1];
        rp[row * 20 + (cp2 >> 1)] = packbf(v0, v1);
        rp[row * 20 + 4 + (tid & 3)] = 0u;   // zero k=8..15
    }
    __syncthreads();

    // ---- gate-gemm: d[128][256] = rpad @ fgB^T; gate cmw in place ---------
    {
        const int w = wid;
        const int col0  = (w % 4) * 32;
        const int mrow0 = (w / 4) * 32;
        const int lrow = lane & 7, lg8 = (lane >> 3) & 1, lg16 = lane >> 4;
        const int r = lane >> 2, c = lane & 3;
        uint32_t a_addr[2];
#pragma unroll
        for (int mt = 0; mt < 2; mt++)
            a_addr[mt] = rpsm + (uint32_t)(mrow0 + mt * 16 + lg8 * 8 + lrow) * 80
                       + lg16 * 16;
#pragma unroll
        for (int nh = 0; nh < 2; nh++) {
            uint32_t b_addr[2];
#pragma unroll
            for (int p = 0; p < 2; p++)
                b_addr[p] = fgBsm +
                    (uint32_t)(nh * 128 + col0 + p * 16 + lg16 * 8 + lrow) * 48
                    + lg8 * 16;
            float acc[2][4][4];
#pragma unroll
            for (int mt = 0; mt < 2; mt++)
#pragma unroll
                for (int nt = 0; nt < 4; nt++)
#pragma unroll
                    for (int i = 0; i < 4; i++) acc[mt][nt][i] = 0.f;
            uint32_t af[2][4];
#pragma unroll
            for (int mt = 0; mt < 2; mt++)
                ldsm4(af[mt][0], af[mt][1], af[mt][2], af[mt][3], a_addr[mt]);
            uint32_t bf[4][2];
#pragma unroll
            for (int p = 0; p < 2; p++)
                ldsm4(bf[2 * p][0], bf[2 * p][1], bf[2 * p + 1][0], bf[2 * p + 1][1],
                      b_addr[p]);
#pragma unroll
            for (int nt = 0; nt < 4; nt++)
#pragma unroll
                for (int mt = 0; mt < 2; mt++)
                    mma16(acc[mt][nt], af[mt], bf[nt][0], bf[nt][1]);
            // gate epilogue: cmw[row][col] *= 2*sigm(d)
#pragma unroll
            for (int mt = 0; mt < 2; mt++) {
                const int row = mrow0 + mt * 16 + r;
#pragma unroll
                for (int nt = 0; nt < 4; nt++) {
                    const int cn = nh * 128 + col0 + nt * 8 + 2 * c;
                    const int wi0 = row * P_CM + (cn >> 1);
                    const int wi1 = (row + 8) * P_CM + (cn >> 1);
                    const float2 u0 = unpkbf(cmw[wi0]);
                    const float2 u1 = unpkbf(cmw[wi1]);
                    cmw[wi0] = packbf(u0.x * 2.0f * sigm(acc[mt][nt][0]),
                                      u0.y * 2.0f * sigm(acc[mt][nt][1]));
                    cmw[wi1] = packbf(u1.x * 2.0f * sigm(acc[mt][nt][2]),
                                      u1.y * 2.0f * sigm(acc[mt][nt][3]));
                }
            }
        }
    }

    // ---- task gate GEMM (buf0); W1c0 already staged in buf1 ----------------
    cp_wait1();
    __syncthreads();   // TG staged + cmw gated, visible to all
    {
        float acc[1][4][4];
#pragma unroll
        for (int nt = 0; nt < 4; nt++)
#pragma unroll
            for (int i = 0; i < 4; i++) acc[0][nt][i] = 0.f;
        mma_chunk<64, 256, P_CM>(acc, cmw, wstA[0], 0, tid);
        epilogue<64, true, false, P_CF>(acc, tg_b1 + t * 64, cfp, tid);
    }
    __syncthreads();
    {
        const int row = tid >> 2, j = tid & 3;
        const float* W = tg_W2 + (size_t)t * 64 * 4;
        float acc = __ldg(&tg_b2[t * 4 + j]);
#pragma unroll 4
        for (int c2 = 0; c2 < 64; c2++)
            acc = fmaf(cfp[row * P_CF + c2], __ldg(&W[c2 * 4 + j]), acc);
        lgb[row * 4 + j] = acc;
    }
    __syncthreads();
    if (tid < ROWS) {
        const float l0 = lgb[tid * 4 + 0], l1 = lgb[tid * 4 + 1];
        const float l2 = lgb[tid * 4 + 2], l3 = lgb[tid * 4 + 3];
        const float m  = fmaxf(fmaxf(l0, l1), fmaxf(l2, l3));
        const float e0f = __expf(l0 - m), e1f = __expf(l1 - m);
        const float e2f = __expf(l2 - m), e3f = __expf(l3 - m);
        const float inv = 1.0f / (e0f + e1f + e2f + e3f);
        gwb[tid * 4 + 0] = e0f * inv; gwb[tid * 4 + 1] = e1f * inv;
        gwb[tid * 4 + 2] = e2f * inv; gwb[tid * 4 + 3] = e3f * inv;
    }
    // next step's barrier publishes gwb before any reader

    // ---- expert loop: 3-step ring per expert (R13 structure) ---------------
    int cur = 1;
    float ag0[8], ag1[8];
#pragma unroll 1
    for (int ep = 0; ep < 4; ep++) {
        const int e = (ep < 2) ? ep : (ep + 2 * g);

        // ---- W1: two 128-K chunks ----
        float acc1[2][4][4];
#pragma unroll
        for (int mt = 0; mt < 2; mt++)
#pragma unroll
            for (int nt = 0; nt < 4; nt++)
#pragma unroll
                for (int i = 0; i < 4; i++) acc1[mt][nt][i] = 0.f;

        cp_wait0(); __syncthreads();
        stage_chunk<128, 16, 32>(wstA[cur ^ 1], g_wimg + IW1 + e * 32768, 1, tid);
        mma_chunk<128, 128, P_CM>(acc1, cmw, wstA[cur], 0, tid);
        cur ^= 1;

        cp_wait0(); __syncthreads();
        stage_chunk<64, 16, 16, false>(wstA[cur ^ 1],
                                       g_wimg + IW2 + e * 8192, 0, tid);
        stage_chunk<64, 8, 8, true>(wstA[cur ^ 1] + W3_OFF,
                                    g_wimg + IW3 + e * 4096, 0, tid);
        mma_chunk<128, 128, P_CM>(acc1, cmw, wstA[cur], 1, tid);
        cur ^= 1;
        epilogue<128, true, true, P_A>(acc1, exp_b1 + e * 128, aw, tid);

        // ---- W2 + W3 (single staged buffer) ----
        float acc2[1][4][4];
#pragma unroll
        for (int nt = 0; nt < 4; nt++)
#pragma unroll
            for (int i = 0; i < 4; i++) acc2[0][nt][i] = 0.f;
        cp_wait0(); __syncthreads();   // W2W3 ready + aw published
        if (ep < 3) {
            const int en = (ep + 1 < 2) ? (ep + 1) : (ep + 1 + 2 * g);
            stage_chunk<128, 16, 32>(wstA[cur ^ 1], g_wimg + IW1 + en * 32768, 0, tid);
        } else {
            stage_chunk<64, 8, 8>(wstA[cur ^ 1], g_wimg + IT1 + t * 4096, 0, tid);
        }
        mma_chunk<64, 128, P_A>(acc2, aw, wstA[cur], 0, tid);
        epilogue<64, true, true, P_B>(acc2, exp_b2 + e * 64, bw, tid);
        __syncthreads();               // publish bw for W3 MMA

        float acc3[1][4][4];
#pragma unroll
        for (int nt = 0; nt < 4; nt++)
#pragma unroll
            for (int i = 0; i < 4; i++) acc3[0][nt][i] = 0.f;
        mma_chunk<64, 64, P_B>(acc3, bw, wstA[cur] + W3_OFF, 0, tid);
        cur ^= 1;
        epilogue<64, false, false, P_CF>(acc3, exp_b3 + e * 64, cfp, tid);
        __syncthreads();               // publish cfp for LN

        // ---- LN + diag self-gate + softmax aggregation ----
        {
            const float* lS  = ln_s + e * 64;
            const float* lB  = ln_b + e * 64;
            const float* sgw = sg_W + (size_t)t * 256;
            const float  sgb = __ldg(&sg_b[t * 4 + ep]);
            const int c0 = 2 * lane, c1 = 2 * lane + 1;
#pragma unroll
            for (int rr2 = 0; rr2 < 8; rr2++) {
                const int row = wid * 8 + rr2;
                const float2 v = *reinterpret_cast<const float2*>(&cfp[row * P_CF + c0]);
                float sum = v.x + v.y;
                float sq  = fmaf(v.x, v.x, v.y * v.y);
#pragma unroll
                for (int o = 16; o; o >>= 1) {
                    sum += __shfl_xor_sync(0xffffffffu, sum, o);
                    sq  += __shfl_xor_sync(0xffffffffu, sq,  o);
                }
                const float mu  = sum * (1.0f / 64.0f);
                const float var = sq * (1.0f / 64.0f) - mu * mu;
                const float inv = rsqrtf(var + 1e-5f);
                const float n0  = fmaf((v.x - mu) * inv, __ldg(&lS[c0]), __ldg(&lB[c0]));
                const float n1  = fmaf((v.y - mu) * inv, __ldg(&lS[c1]), __ldg(&lB[c1]));
                float swp = fmaf(n0, __ldg(&sgw[c0 * 4 + ep]),
                                 n1 * __ldg(&sgw[c1 * 4 + ep]));
#pragma unroll
                for (int o = 16; o; o >>= 1)
                    swp += __shfl_xor_sync(0xffffffffu, swp, o);
                const float scale = (swp + sgb) * gwb[row * 4 + ep];
                if (ep == 0) { ag0[rr2] = n0 * scale;                ag1[rr2] = n1 * scale; }
                else         { ag0[rr2] = fmaf(n0, scale, ag0[rr2]); ag1[rr2] = fmaf(n1, scale, ag1[rr2]); }
            }
        }
    }

    // ---- agg -> bf16 bw ----------------------------------------------------
#pragma unroll
    for (int rr2 = 0; rr2 < 8; rr2++) {
        const int row = wid * 8 + rr2;
        bw[row * P_B + lane] = packbf(ag0[rr2], ag1[rr2]);
    }

    // ---- tower layer 1 (T1 chunk already in flight) -------------------------
    {
        float accT[1][4][4];
#pragma unroll
        for (int nt = 0; nt < 4; nt++)
#pragma unroll
            for (int i = 0; i < 4; i++) accT[0][nt][i] = 0.f;
        cp_wait0(); __syncthreads();   // T1 staged + bw published
        mma_chunk<64, 64, P_B>(accT, bw, wstA[cur], 0, tid);
        epilogue<64, true, false, P_CF>(accT, tw_b1 + t * 64, cfp, tid);
    }
    __syncthreads();
    gemm_t2(cfp, tw_W2 + (size_t)t * 64 * 32, tw_b2 + t * 32, twh2, tid);
    __syncthreads();
    if (tid < ROWS) {
        const float* th = &twh2[tid * P_B];
        const float* W  = tw_W3 + t * 32;
        float acc = __ldg(&tw_b3[t]);
#pragma unroll 4
        for (int c2 = 0; c2 < 32; c2++)
            acc = fmaf(th[c2], __ldg(&W[c2]), acc);
        out[(size_t)(row0 + tid) * 4 + t] = sigm(acc);
    }
}

extern "C" void kernel_launch(void* const* d_in, const int* in_sizes, int n_in,
                              void* d_out, int out_size)
{
    (void)n_in; (void)out_size;
    const float* zs   = (const float*)d_in[0];
    const float* z0   = (const float*)d_in[1];
    const float* z1   = (const float*)d_in[2];
    const float* eW1  = (const float*)d_in[4];
    const float* eb1  = (const float*)d_in[5];
    const float* eW2  = (const float*)d_in[6];
    const float* eb2  = (const float*)d_in[7];
    const float* eW3  = (const float*)d_in[8];
    const float* eb3  = (const float*)d_in[9];
    const float* lns  = (const float*)d_in[10];
    const float* lnb  = (const float*)d_in[11];
    const float* fgA  = (const float*)d_in[12];
    const float* fgB  = (const float*)d_in[13];
    const float* tgW1 = (const float*)d_in[14];
    const float* tgb1 = (const float*)d_in[15];
    const float* tgW2 = (const float*)d_in[16];
    const float* tgb2 = (const float*)d_in[17];
    const float* sgW  = (const float*)d_in[18];
    const float* sgb  = (const float*)d_in[19];
    const float* twW1 = (const float*)d_in[20];
    const float* twb1 = (const float*)d_in[21];
    const float* twW2 = (const float*)d_in[22];
    const float* twb2 = (const float*)d_in[23];
    const float* twW3 = (const float*)d_in[24];
    const float* twb3 = (const float*)d_in[25];

    const int Bn = in_sizes[0] / META;

    prep_all<<<296, 256>>>(eW1, eW2, eW3, tgW1, twW1, fgA, fgB);

    cudaFuncSetAttribute(home_kernel, cudaFuncAttributeMaxDynamicSharedMemorySize,
                         SMEM_TOTAL);
    dim3 grid(Bn / ROWS, 4);
    home_kernel<<<grid, THREADS, SMEM_TOTAL>>>(
        zs, z0, z1, eb1, eb2, eb3, lns, lnb,
        tgb1, tgW2, tgb2, sgW, sgb, twb1, twW2, twb2, twW3, twb3,
        (float*)d_out);
}

// round 16
// speedup vs baseline: 1.7792x; 1.0776x over previous
#include <cuda_runtime.h>
#include <cuda_bf16.h>
#include <cstdint>
#include <cstddef>

#define DINL __device__ __forceinline__

// ---------------------------------------------------------------------------
// HoMESecondLayer v16: v15 with LN alignment fix (float2 loads on pitch-66).
// R14 base + tensorized tower-2 GEMM + fast quarter-row LN epilogue.
// ROWS=128 / 512 threads / 1 CTA/SM.
// ---------------------------------------------------------------------------

constexpr int ROWS    = 128;
constexpr int THREADS = 512;
constexpr int META    = 128;
constexpr int GIN     = 256;

// bf16 weight images in device memory
constexpr int IW1 = 0;                    // 6 x [128][256]
constexpr int IW2 = IW1 + 6 * 128 * 256;  // 6 x [64][128]
constexpr int IW3 = IW2 + 6 * 64 * 128;   // 6 x [64][64]
constexpr int ITG = IW3 + 6 * 64 * 64;    // 4 x [64][256]
constexpr int IT1 = ITG + 4 * 64 * 256;   // 4 x [64][64]
constexpr int IA8 = IT1 + 4 * 64 * 64;    // 4 x [8][256]   fgA^T
constexpr int IB8 = IA8 + 4 * 8 * 256;    // 4 x [256][8]   fgB^T
constexpr int IT2 = IB8 + 4 * 256 * 8;    // 4 x [32][64]   tw_W2^T
constexpr int ITOT = IT2 + 4 * 32 * 64;
__device__ __align__(16) __nv_bfloat16 g_wimg[ITOT];

// smem layout (byte offsets)
constexpr int OFF_WST0 = 0;        // weight ring buf 0 (34816)
constexpr int OFF_WST1 = 34816;    // weight ring buf 1 (34816)
constexpr int OFF_A    = 69632;    // aw region (34816); gating: fgA/fgB/rpad
constexpr int OFF_B    = 104448;   // bw 18432 (also lgb/twh2)
constexpr int OFF_CFP  = 122880;   // cfp 33792 (gating: rl/rh partials)
constexpr int OFF_CMB  = 156672;   // cmw 67584
constexpr int OFF_GW   = 224256;   // gwb 2048
constexpr int SMEM_TOTAL = 226304;
constexpr int W3_OFF   = 17408;    // W3 offset inside merged W2W3 buffer
constexpr int T2_OFF   = 9216;     // T2 offset inside merged T1T2 buffer
// gating overlays
constexpr int GA_OFF = 0;          // fgA img [8][33 u4]
constexpr int GB_OFF = 4224;       // fgB img [256][3 u4]
constexpr int RP_OFF = 16512;      // rpad [128][5 u4]
constexpr int RL_OFF = 0;          // r partials (cfp region)
constexpr int RH_OFF = 4608;

// pitches
constexpr int P_CM = 132;  // words; 33*16B -> LDSM conflict-free
constexpr int P_A  = 68;
constexpr int P_B  = 36;
constexpr int P_CF = 66;

DINL float tanh_ap(float x) {
    float y; asm("tanh.approx.f32 %0, %1;" : "=f"(y) : "f"(x)); return y;
}
DINL float sigm(float x)   { return fmaf(tanh_ap(0.5f * x), 0.5f, 0.5f); }
DINL float swishf(float x) { return x * sigm(x); }
DINL uint32_t sm_addr(const void* p) {
    return (uint32_t)__cvta_generic_to_shared(p);
}
DINL void mma16(float* d, const uint32_t* a, uint32_t b0, uint32_t b1) {
    asm volatile(
        "mma.sync.aligned.m16n8k16.row.col.f32.bf16.bf16.f32 "
        "{%0,%1,%2,%3},{%4,%5,%6,%7},{%8,%9},{%0,%1,%2,%3};"
        : "+f"(d[0]), "+f"(d[1]), "+f"(d[2]), "+f"(d[3])
        : "r"(a[0]), "r"(a[1]), "r"(a[2]), "r"(a[3]), "r"(b0), "r"(b1));
}
DINL void ldsm4(uint32_t& r0, uint32_t& r1, uint32_t& r2, uint32_t& r3,
                uint32_t addr) {
    asm volatile(
        "ldmatrix.sync.aligned.m8n8.x4.shared.b16 {%0,%1,%2,%3}, [%4];"
        : "=r"(r0), "=r"(r1), "=r"(r2), "=r"(r3) : "r"(addr));
}
DINL void ldsm2(uint32_t& r0, uint32_t& r1, uint32_t addr) {
    asm volatile(
        "ldmatrix.sync.aligned.m8n8.x2.shared.b16 {%0,%1}, [%2];"
        : "=r"(r0), "=r"(r1) : "r"(addr));
}
DINL uint32_t packbf(float lo, float hi) {
    __nv_bfloat162 p = __floats2bfloat162_rn(lo, hi);
    return *reinterpret_cast<uint32_t*>(&p);
}
DINL float2 unpkbf(uint32_t w) {
    __nv_bfloat162 b = *reinterpret_cast<__nv_bfloat162*>(&w);
    return __bfloat1622float2(b);
}
DINL void cp16(uint32_t dst, const void* src) {
    asm volatile("cp.async.cg.shared.global [%0], [%1], 16;"
                 :: "r"(dst), "l"(src));
}
DINL void cp_commit() { asm volatile("cp.async.commit_group;" ::: "memory"); }
DINL void cp_wait0()  { asm volatile("cp.async.wait_group 0;" ::: "memory"); }
DINL void cp_wait1()  { asm volatile("cp.async.wait_group 1;" ::: "memory"); }

// ---- merged prep: all weights fp32 -> bf16 transposed images --------------
__global__ void prep_all(const float* __restrict__ eW1,
                         const float* __restrict__ eW2,
                         const float* __restrict__ eW3,
                         const float* __restrict__ tgW1,
                         const float* __restrict__ twW1,
                         const float* __restrict__ fgA,
                         const float* __restrict__ fgB,
                         const float* __restrict__ twW2)
{
    const int SZ1 = 6 * 128 * 256, SZ2 = 6 * 64 * 128, SZ3 = 6 * 64 * 64;
    const int SZ4 = 4 * 64 * 256,  SZ5 = 4 * 64 * 64;
    const int SZ6 = 4 * 8 * 256,   SZ7 = 4 * 256 * 8, SZ8 = 4 * 32 * 64;
    const int total = SZ1 + SZ2 + SZ3 + SZ4 + SZ5 + SZ6 + SZ7 + SZ8;
    for (int gi = blockIdx.x * blockDim.x + threadIdx.x; gi < total;
         gi += gridDim.x * blockDim.x) {
        int idx = gi, dstOff, K, N;
        const float* src;
        if (idx < SZ1)                 { dstOff = IW1; src = eW1;  K = 256; N = 128; }
        else if ((idx -= SZ1) < SZ2)   { dstOff = IW2; src = eW2;  K = 128; N = 64; }
        else if ((idx -= SZ2) < SZ3)   { dstOff = IW3; src = eW3;  K = 64;  N = 64; }
        else if ((idx -= SZ3) < SZ4)   { dstOff = ITG; src = tgW1; K = 256; N = 64; }
        else if ((idx -= SZ4) < SZ5)   { dstOff = IT1; src = twW1; K = 64;  N = 64; }
        else if ((idx -= SZ5) < SZ6)   { dstOff = IA8; src = fgA;  K = 256; N = 8; }
        else if ((idx -= SZ6) < SZ7)   { dstOff = IB8; src = fgB;  K = 8;   N = 256; }
        else         { idx -= SZ7;       dstOff = IT2; src = twW2; K = 64;  N = 32; }
        const int m   = idx / (K * N);
        const int rem = idx - m * (K * N);
        const int n   = rem / K;
        const int k   = rem - n * K;
        g_wimg[dstOff + idx] = __float2bfloat16(src[(size_t)m * K * N + k * N + n]);
    }
}

// ---- cp.async stage of one weight chunk into a ring buffer ----------------
template<int NR, int UPR, int KU, bool COMMIT = true>
DINL void stage_chunk(uint32_t dst, const __nv_bfloat16* Wimg, int kc, int tid)
{
    constexpr int P16   = UPR + 1;
    constexpr int UNITS = NR * UPR / THREADS;
    const uint4* gsrc = reinterpret_cast<const uint4*>(Wimg);
#pragma unroll
    for (int j = 0; j < UNITS; j++) {
        const int i = tid + j * THREADS;
        cp16(dst + (uint32_t)((i / UPR) * P16 + (i % UPR)) * 16,
             gsrc + (i / UPR) * KU + kc * UPR + (i % UPR));
    }
    if (COMMIT) cp_commit();
}
// variant for NR*UPR < THREADS (T2: 32 rows x 8 u4 = 256 units)
template<int NR, int UPR, int KU>
DINL void stage_small(uint32_t dst, const __nv_bfloat16* Wimg, int tid)
{
    constexpr int P16 = UPR + 1;
    const uint4* gsrc = reinterpret_cast<const uint4*>(Wimg);
    if (tid < NR * UPR) {
        const int i = tid;
        cp16(dst + (uint32_t)((i / UPR) * P16 + (i % UPR)) * 16,
             gsrc + (i / UPR) * KU + (i % UPR));
    }
}

// ---- MMA over one staged chunk (CHK K-cols) -------------------------------
template<int N, int CHK, int AP2>
DINL void mma_chunk(float acc[][4][4], const uint32_t* As, uint32_t buf,
                    int kc, int tid)
{
    constexpr int WN  = (N >= 128) ? 4 : 2;
    constexpr int MT  = (N >= 128) ? 2 : 1;
    constexpr int P16 = CHK / 8 + 1;
    const int w = tid >> 5, lane = tid & 31;
    const int col0  = (w % WN) * 32;
    const int mrow0 = (w / WN) * (MT * 16);
    const int lrow = lane & 7, lg8 = (lane >> 3) & 1, lg16 = lane >> 4;

    const uint32_t abase = sm_addr(As);
    uint32_t a_addr[MT];
#pragma unroll
    for (int mt = 0; mt < MT; mt++)
        a_addr[mt] = abase +
            ((mrow0 + mt * 16 + lg8 * 8 + lrow) * AP2 + lg16 * 4) * 4;
    uint32_t b_addr[2];
#pragma unroll
    for (int p = 0; p < 2; p++)
        b_addr[p] = buf +
            (uint32_t)(col0 + p * 16 + lg16 * 8 + lrow) * (P16 * 16) + lg8 * 16;

#pragma unroll
    for (int ks2 = 0; ks2 < CHK / 16; ks2++) {
        const int ksg = kc * (CHK / 16) + ks2;
        uint32_t af[MT][4];
#pragma unroll
        for (int mt = 0; mt < MT; mt++)
            ldsm4(af[mt][0], af[mt][1], af[mt][2], af[mt][3],
                  a_addr[mt] + ksg * 32);
        uint32_t bf[4][2];
#pragma unroll
        for (int p = 0; p < 2; p++)
            ldsm4(bf[2 * p][0], bf[2 * p][1], bf[2 * p + 1][0], bf[2 * p + 1][1],
                  b_addr[p] + ks2 * 32);
#pragma unroll
        for (int nt = 0; nt < 4; nt++)
#pragma unroll
            for (int mt = 0; mt < MT; mt++)
                mma16(acc[mt][nt], af[mt], bf[nt][0], bf[nt][1]);
    }
}

// ---- epilogue: bias (+swish), store fp32 or packed bf16 -------------------
template<int N, bool SW, bool OUTBF, int CP>
DINL void epilogue(float acc[][4][4], const float* __restrict__ bias,
                   void* Cs, int tid)
{
    constexpr int WN = (N >= 128) ? 4 : 2;
    constexpr int MT = (N >= 128) ? 2 : 1;
    const int w = tid >> 5, lane = tid & 31;
    const int col0  = (w % WN) * 32;
    const int mrow0 = (w / WN) * (MT * 16);
    const int r = lane >> 2, c = lane & 3;
#pragma unroll
    for (int mt = 0; mt < MT; mt++) {
        const int row = mrow0 + mt * 16 + r;
#pragma unroll
        for (int nt = 0; nt < 4; nt++) {
            const int cn = col0 + nt * 8 + 2 * c;
            const float bb0 = __ldg(&bias[cn]), bb1 = __ldg(&bias[cn + 1]);
            float v0 = acc[mt][nt][0] + bb0, v1 = acc[mt][nt][1] + bb1;
            float v2 = acc[mt][nt][2] + bb0, v3 = acc[mt][nt][3] + bb1;
            if (SW) { v0 = swishf(v0); v1 = swishf(v1); v2 = swishf(v2); v3 = swishf(v3); }
            if (OUTBF) {
                uint32_t* C = reinterpret_cast<uint32_t*>(Cs);
                C[row * CP + (cn >> 1)]       = packbf(v0, v1);
                C[(row + 8) * CP + (cn >> 1)] = packbf(v2, v3);
            } else {
                float* C = reinterpret_cast<float*>(Cs);
                C[row * CP + cn] = v0; C[row * CP + cn + 1] = v1;
                C[(row + 8) * CP + cn] = v2; C[(row + 8) * CP + cn + 1] = v3;
            }
        }
    }
}

__global__ __launch_bounds__(THREADS, 1)
void home_kernel(
    const float* __restrict__ z_shared, const float* __restrict__ z_g0,
    const float* __restrict__ z_g1,
    const float* __restrict__ exp_b1, const float* __restrict__ exp_b2,
    const float* __restrict__ exp_b3,
    const float* __restrict__ ln_s,   const float* __restrict__ ln_b,
    const float* __restrict__ tg_b1,
    const float* __restrict__ tg_W2,  const float* __restrict__ tg_b2,
    const float* __restrict__ sg_W,   const float* __restrict__ sg_b,
    const float* __restrict__ tw_b1,  const float* __restrict__ tw_b2,
    const float* __restrict__ tw_W3,  const float* __restrict__ tw_b3,
    float* __restrict__ out)
{
    extern __shared__ char sm[];
    uint32_t* cmw  = reinterpret_cast<uint32_t*>(sm + OFF_CMB);
    uint32_t* aw   = reinterpret_cast<uint32_t*>(sm + OFF_A);
    uint32_t* bw   = reinterpret_cast<uint32_t*>(sm + OFF_B);
    float*    cfp  = reinterpret_cast<float*>(sm + OFF_CFP);
    float*    gwb  = reinterpret_cast<float*>(sm + OFF_GW);
    float*    lgb  = reinterpret_cast<float*>(sm + OFF_B);
    float*    twh2 = reinterpret_cast<float*>(sm + OFF_B);
    float*    rl   = reinterpret_cast<float*>(sm + OFF_CFP + RL_OFF);
    float*    rh   = reinterpret_cast<float*>(sm + OFF_CFP + RH_OFF);

    const uint32_t wstA[2] = { sm_addr(sm + OFF_WST0), sm_addr(sm + OFF_WST1) };
    const uint32_t fgAsm = sm_addr(sm + OFF_A + GA_OFF);
    const uint32_t fgBsm = sm_addr(sm + OFF_A + GB_OFF);
    const uint32_t rpsm  = sm_addr(sm + OFF_A + RP_OFF);
    const uint32_t cmbase = sm_addr(cmw);

    const int tid  = threadIdx.x;
    const int wid  = tid >> 5, lane = tid & 31;
    const int t    = blockIdx.y;
    const int g    = t >> 1;                    // TASK_TO_GROUP = {0,0,1,1}
    const int row0 = blockIdx.x * ROWS;
    const float* zg = g ? z_g1 : z_g0;

    // ---- prefetch TG -> buf0 and W1[0]c0 -> buf1 (overlap all gating) ----
    stage_chunk<64, 32, 32>(wstA[0], g_wimg + ITG + t * 16384, 0, tid);
    stage_chunk<128, 16, 32>(wstA[1], g_wimg + IW1, 0, tid);

    // ---- stage fgA/fgB bf16 images into smem ------------------------------
    {
        const uint4* a8 = reinterpret_cast<const uint4*>(g_wimg + IA8 + t * 2048);
        uint4* da = reinterpret_cast<uint4*>(sm + OFF_A + GA_OFF);
        if (tid < 256) {
            const int row = tid >> 5, u = tid & 31;
            da[row * 33 + u] = __ldg(&a8[row * 32 + u]);
        }
        const uint4* b8 = reinterpret_cast<const uint4*>(g_wimg + IB8 + t * 2048);
        uint4* db = reinterpret_cast<uint4*>(sm + OFF_A + GB_OFF);
        const int row = tid >> 1, h = tid & 1;
        db[row * 3 + h] = h ? make_uint4(0, 0, 0, 0) : __ldg(&b8[row]);
    }

    // ---- z -> ungated bf16 cmw --------------------------------------------
#pragma unroll
    for (int j = 0; j < 16; j++) {
        const int idx = tid + j * THREADS;
        const int row = idx >> 6, fc = idx & 63;
        const float4 v = (fc < 32)
            ? *reinterpret_cast<const float4*>(z_shared + (size_t)(row0 + row) * META + fc * 4)
            : *reinterpret_cast<const float4*>(zg + (size_t)(row0 + row) * META + (fc - 32) * 4);
        uint2 o;
        o.x = packbf(v.x, v.y);
        o.y = packbf(v.z, v.w);
        *reinterpret_cast<uint2*>(&cmw[row * P_CM + fc * 2]) = o;
    }
    __syncthreads();

    // ---- r-gemm: r[128][8] = cm @ fgA, K split over warp halves -----------
    {
        const int kh    = wid >> 3;
        const int mrow0 = (wid & 7) * 16;
        const int lrow = lane & 7, lg8 = (lane >> 3) & 1, lg16 = lane >> 4;
        const uint32_t a0 = cmbase + ((mrow0 + lg8 * 8 + lrow) * P_CM + lg16 * 4) * 4;
        const int l2 = lane & 15;
        const uint32_t b0a = fgAsm + (uint32_t)(l2 & 7) * 528 + (l2 >> 3) * 16;
        float acc[4] = {0.f, 0.f, 0.f, 0.f};
#pragma unroll
        for (int ks = 0; ks < 8; ks++) {
            const int ksg = kh * 8 + ks;
            uint32_t af[4];
            ldsm4(af[0], af[1], af[2], af[3], a0 + ksg * 32);
            uint32_t b0, b1;
            ldsm2(b0, b1, b0a + ksg * 32);
            mma16(acc, af, b0, b1);
        }
        const int r = lane >> 2, c = lane & 3;
        float* dst = kh ? rh : rl;
        dst[(mrow0 + r) * 9 + 2 * c]     = acc[0];
        dst[(mrow0 + r) * 9 + 2 * c + 1] = acc[1];
        dst[(mrow0 + r + 8) * 9 + 2 * c]     = acc[2];
        dst[(mrow0 + r + 8) * 9 + 2 * c + 1] = acc[3];
    }
    __syncthreads();

    // ---- combine partials -> rpad -----------------------------------------
    {
        uint32_t* rp = reinterpret_cast<uint32_t*>(sm + OFF_A + RP_OFF);
        const int row = tid >> 2, cp2 = (tid & 3) * 2;
        const float v0 = rl[row * 9 + cp2]     + rh[row * 9 + cp2];
        const float v1 = rl[row * 9 + cp2 + 1] + rh[row * 9 + cp2 + 1];
        rp[row * 20 + (cp2 >> 1)] = packbf(v0, v1);
        rp[row * 20 + 4 + (tid & 3)] = 0u;
    }
    __syncthreads();

    // ---- gate-gemm: d = rpad @ fgB^T; gate cmw in place --------------------
    {
        const int w = wid;
        const int col0  = (w % 4) * 32;
        const int mrow0 = (w / 4) * 32;
        const int lrow = lane & 7, lg8 = (lane >> 3) & 1, lg16 = lane >> 4;
        const int r = lane >> 2, c = lane & 3;
        uint32_t a_addr[2];
#pragma unroll
        for (int mt = 0; mt < 2; mt++)
            a_addr[mt] = rpsm + (uint32_t)(mrow0 + mt * 16 + lg8 * 8 + lrow) * 80
                       + lg16 * 16;
#pragma unroll
        for (int nh = 0; nh < 2; nh++) {
            uint32_t b_addr[2];
#pragma unroll
            for (int p = 0; p < 2; p++)
                b_addr[p] = fgBsm +
                    (uint32_t)(nh * 128 + col0 + p * 16 + lg16 * 8 + lrow) * 48
                    + lg8 * 16;
            float acc[2][4][4];
#pragma unroll
            for (int mt = 0; mt < 2; mt++)
#pragma unroll
                for (int nt = 0; nt < 4; nt++)
#pragma unroll
                    for (int i = 0; i < 4; i++) acc[mt][nt][i] = 0.f;
            uint32_t af[2][4];
#pragma unroll
            for (int mt = 0; mt < 2; mt++)
                ldsm4(af[mt][0], af[mt][1], af[mt][2], af[mt][3], a_addr[mt]);
            uint32_t bf[4][2];
#pragma unroll
            for (int p = 0; p < 2; p++)
                ldsm4(bf[2 * p][0], bf[2 * p][1], bf[2 * p + 1][0], bf[2 * p + 1][1],
                      b_addr[p]);
#pragma unroll
            for (int nt = 0; nt < 4; nt++)
#pragma unroll
                for (int mt = 0; mt < 2; mt++)
                    mma16(acc[mt][nt], af[mt], bf[nt][0], bf[nt][1]);
#pragma unroll
            for (int mt = 0; mt < 2; mt++) {
                const int row = mrow0 + mt * 16 + r;
#pragma unroll
                for (int nt = 0; nt < 4; nt++) {
                    const int cn = nh * 128 + col0 + nt * 8 + 2 * c;
                    const int wi0 = row * P_CM + (cn >> 1);
                    const int wi1 = (row + 8) * P_CM + (cn >> 1);
                    const float2 u0 = unpkbf(cmw[wi0]);
                    const float2 u1 = unpkbf(cmw[wi1]);
                    cmw[wi0] = packbf(u0.x * 2.0f * sigm(acc[mt][nt][0]),
                                      u0.y * 2.0f * sigm(acc[mt][nt][1]));
                    cmw[wi1] = packbf(u1.x * 2.0f * sigm(acc[mt][nt][2]),
                                      u1.y * 2.0f * sigm(acc[mt][nt][3]));
                }
            }
        }
    }

    // ---- task gate GEMM (buf0); W1c0 already staged in buf1 ----------------
    cp_wait1();
    __syncthreads();
    {
        float acc[1][4][4];
#pragma unroll
        for (int nt = 0; nt < 4; nt++)
#pragma unroll
            for (int i = 0; i < 4; i++) acc[0][nt][i] = 0.f;
        mma_chunk<64, 256, P_CM>(acc, cmw, wstA[0], 0, tid);
        epilogue<64, true, false, P_CF>(acc, tg_b1 + t * 64, cfp, tid);
    }
    __syncthreads();
    {
        const int row = tid >> 2, j = tid & 3;
        const float* W = tg_W2 + (size_t)t * 64 * 4;
        float acc = __ldg(&tg_b2[t * 4 + j]);
#pragma unroll 4
        for (int c2 = 0; c2 < 64; c2++)
            acc = fmaf(cfp[row * P_CF + c2], __ldg(&W[c2 * 4 + j]), acc);
        lgb[row * 4 + j] = acc;
    }
    __syncthreads();
    if (tid < ROWS) {
        const float l0 = lgb[tid * 4 + 0], l1 = lgb[tid * 4 + 1];
        const float l2 = lgb[tid * 4 + 2], l3 = lgb[tid * 4 + 3];
        const float m  = fmaxf(fmaxf(l0, l1), fmaxf(l2, l3));
        const float e0f = __expf(l0 - m), e1f = __expf(l1 - m);
        const float e2f = __expf(l2 - m), e3f = __expf(l3 - m);
        const float inv = 1.0f / (e0f + e1f + e2f + e3f);
        gwb[tid * 4 + 0] = e0f * inv; gwb[tid * 4 + 1] = e1f * inv;
        gwb[tid * 4 + 2] = e2f * inv; gwb[tid * 4 + 3] = e3f * inv;
    }

    // ---- expert loop: 3-step ring per expert -------------------------------
    int cur = 1;
    const int lrow_q = tid >> 2;       // LN: row per thread quad
    const int cq     = (tid & 3) * 16; // LN: col base
    float agv[16];
#pragma unroll 1
    for (int ep = 0; ep < 4; ep++) {
        const int e = (ep < 2) ? ep : (ep + 2 * g);

        float acc1[2][4][4];
#pragma unroll
        for (int mt = 0; mt < 2; mt++)
#pragma unroll
            for (int nt = 0; nt < 4; nt++)
#pragma unroll
                for (int i = 0; i < 4; i++) acc1[mt][nt][i] = 0.f;

        cp_wait0(); __syncthreads();
        stage_chunk<128, 16, 32>(wstA[cur ^ 1], g_wimg + IW1 + e * 32768, 1, tid);
        mma_chunk<128, 128, P_CM>(acc1, cmw, wstA[cur], 0, tid);
        cur ^= 1;

        cp_wait0(); __syncthreads();
        stage_chunk<64, 16, 16, false>(wstA[cur ^ 1],
                                       g_wimg + IW2 + e * 8192, 0, tid);
        stage_chunk<64, 8, 8, true>(wstA[cur ^ 1] + W3_OFF,
                                    g_wimg + IW3 + e * 4096, 0, tid);
        mma_chunk<128, 128, P_CM>(acc1, cmw, wstA[cur], 1, tid);
        cur ^= 1;
        epilogue<128, true, true, P_A>(acc1, exp_b1 + e * 128, aw, tid);

        float acc2[1][4][4];
#pragma unroll
        for (int nt = 0; nt < 4; nt++)
#pragma unroll
            for (int i = 0; i < 4; i++) acc2[0][nt][i] = 0.f;
        cp_wait0(); __syncthreads();
        if (ep < 3) {
            const int en = (ep + 1 < 2) ? (ep + 1) : (ep + 1 + 2 * g);
            stage_chunk<128, 16, 32>(wstA[cur ^ 1], g_wimg + IW1 + en * 32768, 0, tid);
        } else {
            stage_chunk<64, 8, 8, false>(wstA[cur ^ 1], g_wimg + IT1 + t * 4096, 0, tid);
            stage_small<32, 8, 8>(wstA[cur ^ 1] + T2_OFF, g_wimg + IT2 + t * 2048, tid);
            cp_commit();
        }
        mma_chunk<64, 128, P_A>(acc2, aw, wstA[cur], 0, tid);
        epilogue<64, true, true, P_B>(acc2, exp_b2 + e * 64, bw, tid);
        __syncthreads();

        float acc3[1][4][4];
#pragma unroll
        for (int nt = 0; nt < 4; nt++)
#pragma unroll
            for (int i = 0; i < 4; i++) acc3[0][nt][i] = 0.f;
        mma_chunk<64, 64, P_B>(acc3, bw, wstA[cur] + W3_OFF, 0, tid);
        cur ^= 1;
        epilogue<64, false, false, P_CF>(acc3, exp_b3 + e * 64, cfp, tid);
        __syncthreads();

        // ---- fast LN + diag self-gate + softmax aggregation (float2 loads) --
        {
            const float* lS  = ln_s + e * 64 + cq;
            const float* lB  = ln_b + e * 64 + cq;
            const float* sgw = sg_W + (size_t)t * 256;
            const float  sgb = __ldg(&sg_b[t * 4 + ep]);
            const float* src = &cfp[lrow_q * P_CF + cq];
            float n[16];
            float sum = 0.f, sq = 0.f;
#pragma unroll
            for (int i = 0; i < 16; i += 2) {
                const float2 v2 = *reinterpret_cast<const float2*>(src + i);
                n[i] = v2.x; n[i + 1] = v2.y;
                sum += v2.x + v2.y;
                sq = fmaf(v2.x, v2.x, fmaf(v2.y, v2.y, sq));
            }
            sum += __shfl_xor_sync(0xffffffffu, sum, 1);
            sq  += __shfl_xor_sync(0xffffffffu, sq,  1);
            sum += __shfl_xor_sync(0xffffffffu, sum, 2);
            sq  += __shfl_xor_sync(0xffffffffu, sq,  2);
            const float mu  = sum * (1.0f / 64.0f);
            const float var = sq * (1.0f / 64.0f) - mu * mu;
            const float inv = rsqrtf(var + 1e-5f);
            float swp = 0.f;
#pragma unroll
            for (int i = 0; i < 16; i++) {
                n[i] = fmaf((n[i] - mu) * inv, __ldg(&lS[i]), __ldg(&lB[i]));
                swp = fmaf(n[i], __ldg(&sgw[(cq + i) * 4 + ep]), swp);
            }
            swp += __shfl_xor_sync(0xffffffffu, swp, 1);
            swp += __shfl_xor_sync(0xffffffffu, swp, 2);
            const float scale = (swp + sgb) * gwb[lrow_q * 4 + ep];
            if (ep == 0) {
#pragma unroll
                for (int i = 0; i < 16; i++) agv[i] = n[i] * scale;
            } else {
#pragma unroll
                for (int i = 0; i < 16; i++) agv[i] = fmaf(n[i], scale, agv[i]);
            }
        }
    }

    // ---- agg -> bf16 bw -----------------------------------------------------
    {
        uint4 o0, o1;
        o0.x = packbf(agv[0], agv[1]);   o0.y = packbf(agv[2], agv[3]);
        o0.z = packbf(agv[4], agv[5]);   o0.w = packbf(agv[6], agv[7]);
        o1.x = packbf(agv[8], agv[9]);   o1.y = packbf(agv[10], agv[11]);
        o1.z = packbf(agv[12], agv[13]); o1.w = packbf(agv[14], agv[15]);
        uint4* dst = reinterpret_cast<uint4*>(&bw[lrow_q * P_B + (tid & 3) * 8]);
        dst[0] = o0; dst[1] = o1;
    }

    // ---- tower layer 1 (T1/T2 chunks already in flight) ---------------------
    {
        float accT[1][4][4];
#pragma unroll
        for (int nt = 0; nt < 4; nt++)
#pragma unroll
            for (int i = 0; i < 4; i++) accT[0][nt][i] = 0.f;
        cp_wait0(); __syncthreads();   // T1+T2 staged + bw published
        mma_chunk<64, 64, P_B>(accT, bw, wstA[cur], 0, tid);
        epilogue<64, true, true, P_A>(accT, tw_b1 + t * 64, aw, tid);
    }
    __syncthreads();   // publish aw (bf16 tower h1)

    // ---- tower layer 2 via mma (N=32, K=64) --------------------------------
    {
        const int col0  = (wid & 1) * 16;
        const int mrow0 = (wid >> 1) * 16;
        const int lrow = lane & 7, lg8 = (lane >> 3) & 1, lg16 = lane >> 4;
        const uint32_t a0 = sm_addr(aw) +
            ((mrow0 + lg8 * 8 + lrow) * P_A + lg16 * 4) * 4;
        const uint32_t b0 = wstA[cur] + T2_OFF +
            (uint32_t)(col0 + lg16 * 8 + lrow) * 144 + lg8 * 16;
        float acc[2][4];
#pragma unroll
        for (int nt = 0; nt < 2; nt++)
#pragma unroll
            for (int i = 0; i < 4; i++) acc[nt][i] = 0.f;
#pragma unroll
        for (int ks = 0; ks < 4; ks++) {
            uint32_t af[4];
            ldsm4(af[0], af[1], af[2], af[3], a0 + ks * 32);
            uint32_t bf[4];
            ldsm4(bf[0], bf[1], bf[2], bf[3], b0 + ks * 32);
            mma16(acc[0], af, bf[0], bf[1]);
            mma16(acc[1], af, bf[2], bf[3]);
        }
        const int r = lane >> 2, c = lane & 3;
#pragma unroll
        for (int nt = 0; nt < 2; nt++) {
            const int cn = col0 + nt * 8 + 2 * c;
            const float bb0 = __ldg(&tw_b2[t * 32 + cn]);
            const float bb1 = __ldg(&tw_b2[t * 32 + cn + 1]);
            twh2[(mrow0 + r) * P_B + cn]     = swishf(acc[nt][0] + bb0);
            twh2[(mrow0 + r) * P_B + cn + 1] = swishf(acc[nt][1] + bb1);
            twh2[(mrow0 + r + 8) * P_B + cn]     = swishf(acc[nt][2] + bb0);
            twh2[(mrow0 + r + 8) * P_B + cn + 1] = swishf(acc[nt][3] + bb1);
        }
    }
    __syncthreads();
    if (tid < ROWS) {
        const float* th = &twh2[tid * P_B];
        const float* W  = tw_W3 + t * 32;
        float acc = __ldg(&tw_b3[t]);
#pragma unroll 4
        for (int c2 = 0; c2 < 32; c2++)
            acc = fmaf(th[c2], __ldg(&W[c2]), acc);
        out[(size_t)(row0 + tid) * 4 + t] = sigm(acc);
    }
}

extern "C" void kernel_launch(void* const* d_in, const int* in_sizes, int n_in,
                              void* d_out, int out_size)
{
    (void)n_in; (void)out_size;
    const float* zs   = (const float*)d_in[0];
    const float* z0   = (const float*)d_in[1];
    const float* z1   = (const float*)d_in[2];
    const float* eW1  = (const float*)d_in[4];
    const float* eb1  = (const float*)d_in[5];
    const float* eW2  = (const float*)d_in[6];
    const float* eb2  = (const float*)d_in[7];
    const float* eW3  = (const float*)d_in[8];
    const float* eb3  = (const float*)d_in[9];
    const float* lns  = (const float*)d_in[10];
    const float* lnb  = (const float*)d_in[11];
    const float* fgA  = (const float*)d_in[12];
    const float* fgB  = (const float*)d_in[13];
    const float* tgW1 = (const float*)d_in[14];
    const float* tgb1 = (const float*)d_in[15];
    const float* tgW2 = (const float*)d_in[16];
    const float* tgb2 = (const float*)d_in[17];
    const float* sgW  = (const float*)d_in[18];
    const float* sgb  = (const float*)d_in[19];
    const float* twW1 = (const float*)d_in[20];
    const float* twb1 = (const float*)d_in[21];
    const float* twW2 = (const float*)d_in[22];
    const float* twb2 = (const float*)d_in[23];
    const float* twW3 = (const float*)d_in[24];
    const float* twb3 = (const float*)d_in[25];

    const int Bn = in_sizes[0] / META;

    prep_all<<<296, 256>>>(eW1, eW2, eW3, tgW1, twW1, fgA, fgB, twW2);

    cudaFuncSetAttribute(home_kernel, cudaFuncAttributeMaxDynamicSharedMemorySize,
                         SMEM_TOTAL);
    dim3 grid(Bn / ROWS, 4);
    home_kernel<<<grid, THREADS, SMEM_TOTAL>>>(
        zs, z0, z1, eb1, eb2, eb3, lns, lnb,
        tgb1, tgW2, tgb2, sgW, sgb, twb1, twb2, twW3, twb3,
        (float*)d_out);
}

// round 17
// speedup vs baseline: 1.9219x; 1.0802x over previous
#include <cuda_runtime.h>
#include <cuda_bf16.h>
#include <cstdint>
#include <cstddef>

#define DINL __device__ __forceinline__

// ---------------------------------------------------------------------------
// HoMESecondLayer v17: 2 CTAs/SM. ROWS=64 / 256 threads, uniform 64-K ring
// (W2 full-K), cfp overlaid on aw. Tensorized gating/T2, fast LN (v16 logic).
// ---------------------------------------------------------------------------

constexpr int ROWS    = 64;
constexpr int THREADS = 256;
constexpr int META    = 128;

// bf16 weight images in device memory
constexpr int IW1 = 0;                    // 6 x [128][256]
constexpr int IW2 = IW1 + 6 * 128 * 256;  // 6 x [64][128]
constexpr int IW3 = IW2 + 6 * 64 * 128;   // 6 x [64][64]
constexpr int ITG = IW3 + 6 * 64 * 64;    // 4 x [64][256]
constexpr int IT1 = ITG + 4 * 64 * 256;   // 4 x [64][64]
constexpr int IA8 = IT1 + 4 * 64 * 64;    // 4 x [8][256]   fgA^T
constexpr int IB8 = IA8 + 4 * 8 * 256;    // 4 x [256][8]   fgB^T
constexpr int IT2 = IB8 + 4 * 256 * 8;    // 4 x [32][64]   tw_W2^T
constexpr int ITOT = IT2 + 4 * 32 * 64;
__device__ __align__(16) __nv_bfloat16 g_wimg[ITOT];

// smem layout (byte offsets), total 103424 -> 2 CTAs/SM
constexpr int OFF_WST0 = 0;        // ring buf 0 (18432)
constexpr int OFF_WST1 = 18432;    // ring buf 1 (18432)
constexpr int OFF_A    = 36864;    // aw 64*68w = 17408 (also cfp / fgA+fgB)
constexpr int OFF_B    = 54272;    // bw 64*36w = 9216 (also rl/rh, lgb, twh2)
constexpr int OFF_CMB  = 63488;    // cmw 64*132w = 33792
constexpr int OFF_GW   = 97280;    // gwb 1024
constexpr int OFF_RP   = 98304;    // rpad 64*5u4 = 5120
constexpr int SMEM_TOTAL = 103424;
constexpr int SUB_OFF  = 9216;     // 2nd sub-chunk offset inside a ring buf
// overlays
constexpr int GA_OFF = 0;          // in aw: fgA img [8][33 u4] = 4224
constexpr int GB_OFF = 4224;       // in aw: fgB img [256][3 u4] = 12288
constexpr int RL_OFF = 0;          // in bw: [64][9] f32 = 2304
constexpr int RH_OFF = 4608;       // in bw

// pitches (32-bit words)
constexpr int P_CM = 132;
constexpr int P_A  = 68;
constexpr int P_B  = 36;
constexpr int P_CF = 66;

DINL float tanh_ap(float x) {
    float y; asm("tanh.approx.f32 %0, %1;" : "=f"(y) : "f"(x)); return y;
}
DINL float sigm(float x)   { return fmaf(tanh_ap(0.5f * x), 0.5f, 0.5f); }
DINL float swishf(float x) { return x * sigm(x); }
DINL uint32_t sm_addr(const void* p) {
    return (uint32_t)__cvta_generic_to_shared(p);
}
DINL void mma16(float* d, const uint32_t* a, uint32_t b0, uint32_t b1) {
    asm volatile(
        "mma.sync.aligned.m16n8k16.row.col.f32.bf16.bf16.f32 "
        "{%0,%1,%2,%3},{%4,%5,%6,%7},{%8,%9},{%0,%1,%2,%3};"
        : "+f"(d[0]), "+f"(d[1]), "+f"(d[2]), "+f"(d[3])
        : "r"(a[0]), "r"(a[1]), "r"(a[2]), "r"(a[3]), "r"(b0), "r"(b1));
}
DINL void ldsm4(uint32_t& r0, uint32_t& r1, uint32_t& r2, uint32_t& r3,
                uint32_t addr) {
    asm volatile(
        "ldmatrix.sync.aligned.m8n8.x4.shared.b16 {%0,%1,%2,%3}, [%4];"
        : "=r"(r0), "=r"(r1), "=r"(r2), "=r"(r3) : "r"(addr));
}
DINL void ldsm2(uint32_t& r0, uint32_t& r1, uint32_t addr) {
    asm volatile(
        "ldmatrix.sync.aligned.m8n8.x2.shared.b16 {%0,%1}, [%2];"
        : "=r"(r0), "=r"(r1) : "r"(addr));
}
DINL uint32_t packbf(float lo, float hi) {
    __nv_bfloat162 p = __floats2bfloat162_rn(lo, hi);
    return *reinterpret_cast<uint32_t*>(&p);
}
DINL float2 unpkbf(uint32_t w) {
    __nv_bfloat162 b = *reinterpret_cast<__nv_bfloat162*>(&w);
    return __bfloat1622float2(b);
}
DINL void cp16(uint32_t dst, const void* src) {
    asm volatile("cp.async.cg.shared.global [%0], [%1], 16;"
                 :: "r"(dst), "l"(src));
}
DINL void cp_commit() { asm volatile("cp.async.commit_group;" ::: "memory"); }
DINL void cp_wait0()  { asm volatile("cp.async.wait_group 0;" ::: "memory"); }
DINL void cp_wait1()  { asm volatile("cp.async.wait_group 1;" ::: "memory"); }

// ---- merged prep: all weights fp32 -> bf16 transposed images --------------
__global__ void prep_all(const float* __restrict__ eW1,
                         const float* __restrict__ eW2,
                         const float* __restrict__ eW3,
                         const float* __restrict__ tgW1,
                         const float* __restrict__ twW1,
                         const float* __restrict__ fgA,
                         const float* __restrict__ fgB,
                         const float* __restrict__ twW2)
{
    const int SZ1 = 6 * 128 * 256, SZ2 = 6 * 64 * 128, SZ3 = 6 * 64 * 64;
    const int SZ4 = 4 * 64 * 256,  SZ5 = 4 * 64 * 64;
    const int SZ6 = 4 * 8 * 256,   SZ7 = 4 * 256 * 8, SZ8 = 4 * 32 * 64;
    const int total = SZ1 + SZ2 + SZ3 + SZ4 + SZ5 + SZ6 + SZ7 + SZ8;
    for (int gi = blockIdx.x * blockDim.x + threadIdx.x; gi < total;
         gi += gridDim.x * blockDim.x) {
        int idx = gi, dstOff, K, N;
        const float* src;
        if (idx < SZ1)                 { dstOff = IW1; src = eW1;  K = 256; N = 128; }
        else if ((idx -= SZ1) < SZ2)   { dstOff = IW2; src = eW2;  K = 128; N = 64; }
        else if ((idx -= SZ2) < SZ3)   { dstOff = IW3; src = eW3;  K = 64;  N = 64; }
        else if ((idx -= SZ3) < SZ4)   { dstOff = ITG; src = tgW1; K = 256; N = 64; }
        else if ((idx -= SZ4) < SZ5)   { dstOff = IT1; src = twW1; K = 64;  N = 64; }
        else if ((idx -= SZ5) < SZ6)   { dstOff = IA8; src = fgA;  K = 256; N = 8; }
        else if ((idx -= SZ6) < SZ7)   { dstOff = IB8; src = fgB;  K = 8;   N = 256; }
        else         { idx -= SZ7;       dstOff = IT2; src = twW2; K = 64;  N = 32; }
        const int m   = idx / (K * N);
        const int rem = idx - m * (K * N);
        const int n   = rem / K;
        const int k   = rem - n * K;
        g_wimg[dstOff + idx] = __float2bfloat16(src[(size_t)m * K * N + k * N + n]);
    }
}

// ---- cp.async stage of one weight chunk into a ring buffer ----------------
template<int NR, int UPR, int KU, bool COMMIT = true>
DINL void stage_chunk(uint32_t dst, const __nv_bfloat16* Wimg, int kc, int tid)
{
    constexpr int P16   = UPR + 1;
    constexpr int UNITS = NR * UPR / THREADS;
    const uint4* gsrc = reinterpret_cast<const uint4*>(Wimg);
#pragma unroll
    for (int j = 0; j < UNITS; j++) {
        const int i = tid + j * THREADS;
        cp16(dst + (uint32_t)((i / UPR) * P16 + (i % UPR)) * 16,
             gsrc + (i / UPR) * KU + kc * UPR + (i % UPR));
    }
    if (COMMIT) cp_commit();
}
// T2: 32 rows x 8 u4 = 256 units = THREADS
template<int NR, int UPR, int KU>
DINL void stage_small(uint32_t dst, const __nv_bfloat16* Wimg, int tid)
{
    constexpr int P16 = UPR + 1;
    const uint4* gsrc = reinterpret_cast<const uint4*>(Wimg);
    if (tid < NR * UPR) {
        const int i = tid;
        cp16(dst + (uint32_t)((i / UPR) * P16 + (i % UPR)) * 16,
             gsrc + (i / UPR) * KU + (i % UPR));
    }
}

// ---- MMA over one staged chunk (CHK K-cols), 8 warps, 64 rows --------------
template<int N, int CHK, int AP2>
DINL void mma_chunk(float acc[][4][4], const uint32_t* As, uint32_t buf,
                    int kc, int tid)
{
    constexpr int WN  = (N >= 128) ? 4 : 2;
    constexpr int MT  = (N >= 128) ? 2 : 1;
    constexpr int P16 = CHK / 8 + 1;
    const int w = tid >> 5, lane = tid & 31;
    const int col0  = (w % WN) * 32;
    const int mrow0 = (w / WN) * (MT * 16);
    const int lrow = lane & 7, lg8 = (lane >> 3) & 1, lg16 = lane >> 4;

    const uint32_t abase = sm_addr(As);
    uint32_t a_addr[MT];
#pragma unroll
    for (int mt = 0; mt < MT; mt++)
        a_addr[mt] = abase +
            ((mrow0 + mt * 16 + lg8 * 8 + lrow) * AP2 + lg16 * 4) * 4;
    uint32_t b_addr[2];
#pragma unroll
    for (int p = 0; p < 2; p++)
        b_addr[p] = buf +
            (uint32_t)(col0 + p * 16 + lg16 * 8 + lrow) * (P16 * 16) + lg8 * 16;

#pragma unroll
    for (int ks2 = 0; ks2 < CHK / 16; ks2++) {
        const int ksg = kc * (CHK / 16) + ks2;
        uint32_t af[MT][4];
#pragma unroll
        for (int mt = 0; mt < MT; mt++)
            ldsm4(af[mt][0], af[mt][1], af[mt][2], af[mt][3],
                  a_addr[mt] + ksg * 32);
        uint32_t bf[4][2];
#pragma unroll
        for (int p = 0; p < 2; p++)
            ldsm4(bf[2 * p][0], bf[2 * p][1], bf[2 * p + 1][0], bf[2 * p + 1][1],
                  b_addr[p] + ks2 * 32);
#pragma unroll
        for (int nt = 0; nt < 4; nt++)
#pragma unroll
            for (int mt = 0; mt < MT; mt++)
                mma16(acc[mt][nt], af[mt], bf[nt][0], bf[nt][1]);
    }
}

// ---- epilogue: bias (+swish), store fp32 or packed bf16 -------------------
template<int N, bool SW, bool OUTBF, int CP>
DINL void epilogue(float acc[][4][4], const float* __restrict__ bias,
                   void* Cs, int tid)
{
    constexpr int WN = (N >= 128) ? 4 : 2;
    constexpr int MT = (N >= 128) ? 2 : 1;
    const int w = tid >> 5, lane = tid & 31;
    const int col0  = (w % WN) * 32;
    const int mrow0 = (w / WN) * (MT * 16);
    const int r = lane >> 2, c = lane & 3;
#pragma unroll
    for (int mt = 0; mt < MT; mt++) {
        const int row = mrow0 + mt * 16 + r;
#pragma unroll
        for (int nt = 0; nt < 4; nt++) {
            const int cn = col0 + nt * 8 + 2 * c;
            const float bb0 = __ldg(&bias[cn]), bb1 = __ldg(&bias[cn + 1]);
            float v0 = acc[mt][nt][0] + bb0, v1 = acc[mt][nt][1] + bb1;
            float v2 = acc[mt][nt][2] + bb0, v3 = acc[mt][nt][3] + bb1;
            if (SW) { v0 = swishf(v0); v1 = swishf(v1); v2 = swishf(v2); v3 = swishf(v3); }
            if (OUTBF) {
                uint32_t* C = reinterpret_cast<uint32_t*>(Cs);
                C[row * CP + (cn >> 1)]       = packbf(v0, v1);
                C[(row + 8) * CP + (cn >> 1)] = packbf(v2, v3);
            } else {
                float* C = reinterpret_cast<float*>(Cs);
                C[row * CP + cn] = v0; C[row * CP + cn + 1] = v1;
                C[(row + 8) * CP + cn] = v2; C[(row + 8) * CP + cn + 1] = v3;
            }
        }
    }
}

__global__ __launch_bounds__(THREADS, 2)
void home_kernel(
    const float* __restrict__ z_shared, const float* __restrict__ z_g0,
    const float* __restrict__ z_g1,
    const float* __restrict__ exp_b1, const float* __restrict__ exp_b2,
    const float* __restrict__ exp_b3,
    const float* __restrict__ ln_s,   const float* __restrict__ ln_b,
    const float* __restrict__ tg_b1,
    const float* __restrict__ tg_W2,  const float* __restrict__ tg_b2,
    const float* __restrict__ sg_W,   const float* __restrict__ sg_b,
    const float* __restrict__ tw_b1,  const float* __restrict__ tw_b2,
    const float* __restrict__ tw_W3,  const float* __restrict__ tw_b3,
    float* __restrict__ out)
{
    extern __shared__ char sm[];
    uint32_t* cmw  = reinterpret_cast<uint32_t*>(sm + OFF_CMB);
    uint32_t* aw   = reinterpret_cast<uint32_t*>(sm + OFF_A);
    uint32_t* bw   = reinterpret_cast<uint32_t*>(sm + OFF_B);
    float*    cfp  = reinterpret_cast<float*>(sm + OFF_A);   // overlay on aw
    float*    gwb  = reinterpret_cast<float*>(sm + OFF_GW);
    float*    lgb  = reinterpret_cast<float*>(sm + OFF_B);
    float*    twh2 = reinterpret_cast<float*>(sm + OFF_B);
    float*    rl   = reinterpret_cast<float*>(sm + OFF_B + RL_OFF);
    float*    rh   = reinterpret_cast<float*>(sm + OFF_B + RH_OFF);

    const uint32_t wstA[2] = { sm_addr(sm + OFF_WST0), sm_addr(sm + OFF_WST1) };
    const uint32_t fgAsm = sm_addr(sm + OFF_A + GA_OFF);
    const uint32_t fgBsm = sm_addr(sm + OFF_A + GB_OFF);
    const uint32_t rpsm  = sm_addr(sm + OFF_RP);
    const uint32_t cmbase = sm_addr(cmw);

    const int tid  = threadIdx.x;
    const int wid  = tid >> 5, lane = tid & 31;
    const int t    = blockIdx.y;
    const int g    = t >> 1;                    // TASK_TO_GROUP = {0,0,1,1}
    const int row0 = blockIdx.x * ROWS;
    const float* zg = g ? z_g1 : z_g0;

    // ---- prefetch TG chunks 0,1 -> buf0 and 2,3 -> buf1 --------------------
    stage_chunk<64, 8, 32, false>(wstA[0], g_wimg + ITG + t * 16384, 0, tid);
    stage_chunk<64, 8, 32, true >(wstA[0] + SUB_OFF, g_wimg + ITG + t * 16384, 1, tid);
    stage_chunk<64, 8, 32, false>(wstA[1], g_wimg + ITG + t * 16384, 2, tid);
    stage_chunk<64, 8, 32, true >(wstA[1] + SUB_OFF, g_wimg + ITG + t * 16384, 3, tid);

    // ---- stage fgA/fgB bf16 images into smem (aw region) -------------------
    {
        const uint4* a8 = reinterpret_cast<const uint4*>(g_wimg + IA8 + t * 2048);
        uint4* da = reinterpret_cast<uint4*>(sm + OFF_A + GA_OFF);
        const int row = tid >> 5, u = tid & 31;
        da[row * 33 + u] = __ldg(&a8[row * 32 + u]);
        const uint4* b8 = reinterpret_cast<const uint4*>(g_wimg + IB8 + t * 2048);
        uint4* db = reinterpret_cast<uint4*>(sm + OFF_A + GB_OFF);
#pragma unroll
        for (int j = 0; j < 2; j++) {
            const int idx = tid + j * THREADS;
            const int brow = idx >> 1, h = idx & 1;
            db[brow * 3 + h] = h ? make_uint4(0, 0, 0, 0) : __ldg(&b8[brow]);
        }
    }

    // ---- z -> ungated bf16 cmw ---------------------------------------------
#pragma unroll
    for (int j = 0; j < 16; j++) {
        const int idx = tid + j * THREADS;
        const int row = idx >> 6, fc = idx & 63;
        const float4 v = (fc < 32)
            ? *reinterpret_cast<const float4*>(z_shared + (size_t)(row0 + row) * META + fc * 4)
            : *reinterpret_cast<const float4*>(zg + (size_t)(row0 + row) * META + (fc - 32) * 4);
        uint2 o;
        o.x = packbf(v.x, v.y);
        o.y = packbf(v.z, v.w);
        *reinterpret_cast<uint2*>(&cmw[row * P_CM + fc * 2]) = o;
    }
    __syncthreads();

    // ---- r-gemm: r[64][8] = cm @ fgA, K split over warp halves -------------
    {
        const int kh    = wid >> 2;            // 0: k 0-127, 1: k 128-255
        const int mrow0 = (wid & 3) * 16;
        const int lrow = lane & 7, lg8 = (lane >> 3) & 1, lg16 = lane >> 4;
        const uint32_t a0 = cmbase + ((mrow0 + lg8 * 8 + lrow) * P_CM + lg16 * 4) * 4;
        const int l2 = lane & 15;
        const uint32_t b0a = fgAsm + (uint32_t)(l2 & 7) * 528 + (l2 >> 3) * 16;
        float acc[4] = {0.f, 0.f, 0.f, 0.f};
#pragma unroll
        for (int ks = 0; ks < 8; ks++) {
            const int ksg = kh * 8 + ks;
            uint32_t af[4];
            ldsm4(af[0], af[1], af[2], af[3], a0 + ksg * 32);
            uint32_t b0, b1;
            ldsm2(b0, b1, b0a + ksg * 32);
            mma16(acc, af, b0, b1);
        }
        const int r = lane >> 2, c = lane & 3;
        float* dst = kh ? rh : rl;
        dst[(mrow0 + r) * 9 + 2 * c]     = acc[0];
        dst[(mrow0 + r) * 9 + 2 * c + 1] = acc[1];
        dst[(mrow0 + r + 8) * 9 + 2 * c]     = acc[2];
        dst[(mrow0 + r + 8) * 9 + 2 * c + 1] = acc[3];
    }
    __syncthreads();

    // ---- combine partials -> rpad [64][5 u4] -------------------------------
    {
        uint32_t* rp = reinterpret_cast<uint32_t*>(sm + OFF_RP);
        const int row = tid >> 2, cp2 = (tid & 3) * 2;
        const float v0 = rl[row * 9 + cp2]     + rh[row * 9 + cp2];
        const float v1 = rl[row * 9 + cp2 + 1] + rh[row * 9 + cp2 + 1];
        rp[row * 20 + (cp2 >> 1)] = packbf(v0, v1);
        rp[row * 20 + 4 + (tid & 3)] = 0u;
    }
    __syncthreads();

    // ---- gate-gemm: d = rpad @ fgB^T; gate cmw in place --------------------
    {
        const int col0  = (wid % 4) * 32;
        const int mrow0 = (wid / 4) * 32;
        const int lrow = lane & 7, lg8 = (lane >> 3) & 1, lg16 = lane >> 4;
        const int r = lane >> 2, c = lane & 3;
        uint32_t a_addr[2];
#pragma unroll
        for (int mt = 0; mt < 2; mt++)
            a_addr[mt] = rpsm + (uint32_t)(mrow0 + mt * 16 + lg8 * 8 + lrow) * 80
                       + lg16 * 16;
#pragma unroll
        for (int nh = 0; nh < 2; nh++) {
            uint32_t b_addr[2];
#pragma unroll
            for (int p = 0; p < 2; p++)
                b_addr[p] = fgBsm +
                    (uint32_t)(nh * 128 + col0 + p * 16 + lg16 * 8 + lrow) * 48
                    + lg8 * 16;
            float acc[2][4][4];
#pragma unroll
            for (int mt = 0; mt < 2; mt++)
#pragma unroll
                for (int nt = 0; nt < 4; nt++)
#pragma unroll
                    for (int i = 0; i < 4; i++) acc[mt][nt][i] = 0.f;
            uint32_t af[2][4];
#pragma unroll
            for (int mt = 0; mt < 2; mt++)
                ldsm4(af[mt][0], af[mt][1], af[mt][2], af[mt][3], a_addr[mt]);
            uint32_t bf[4][2];
#pragma unroll
            for (int p = 0; p < 2; p++)
                ldsm4(bf[2 * p][0], bf[2 * p][1], bf[2 * p + 1][0], bf[2 * p + 1][1],
                      b_addr[p]);
#pragma unroll
            for (int nt = 0; nt < 4; nt++)
#pragma unroll
                for (int mt = 0; mt < 2; mt++)
                    mma16(acc[mt][nt], af[mt], bf[nt][0], bf[nt][1]);
#pragma unroll
            for (int mt = 0; mt < 2; mt++) {
                const int row = mrow0 + mt * 16 + r;
#pragma unroll
                for (int nt = 0; nt < 4; nt++) {
                    const int cn = nh * 128 + col0 + nt * 8 + 2 * c;
                    const int wi0 = row * P_CM + (cn >> 1);
                    const int wi1 = (row + 8) * P_CM + (cn >> 1);
                    const float2 u0 = unpkbf(cmw[wi0]);
                    const float2 u1 = unpkbf(cmw[wi1]);
                    cmw[wi0] = packbf(u0.x * 2.0f * sigm(acc[mt][nt][0]),
                                      u0.y * 2.0f * sigm(acc[mt][nt][1]));
                    cmw[wi1] = packbf(u1.x * 2.0f * sigm(acc[mt][nt][2]),
                                      u1.y * 2.0f * sigm(acc[mt][nt][3]));
                }
            }
        }
    }

    // ---- TG GEMM: 4 x 64-K sub-chunks across buf0/buf1 ---------------------
    float accT[1][4][4];
#pragma unroll
    for (int nt = 0; nt < 4; nt++)
#pragma unroll
        for (int i = 0; i < 4; i++) accT[0][nt][i] = 0.f;
    cp_wait1();        // TG c0,c1 landed
    __syncthreads();   // + cmw gated visible
    mma_chunk<64, 64, P_CM>(accT, cmw, wstA[0], 0, tid);
    mma_chunk<64, 64, P_CM>(accT, cmw, wstA[0] + SUB_OFF, 1, tid);
    cp_wait0();        // TG c2,c3 landed
    __syncthreads();   // buf0 consumers done -> restage
    stage_chunk<128, 8, 32>(wstA[0], g_wimg + IW1, 0, tid);   // W1[e0]c0
    mma_chunk<64, 64, P_CM>(accT, cmw, wstA[1], 2, tid);
    mma_chunk<64, 64, P_CM>(accT, cmw, wstA[1] + SUB_OFF, 3, tid);
    epilogue<64, true, false, P_CF>(accT, tg_b1 + t * 64, cfp, tid);
    __syncthreads();
    {
        const int row = tid >> 2, j = tid & 3;
        const float* W = tg_W2 + (size_t)t * 64 * 4;
        float acc = __ldg(&tg_b2[t * 4 + j]);
#pragma unroll 4
        for (int c2 = 0; c2 < 64; c2++)
            acc = fmaf(cfp[row * P_CF + c2], __ldg(&W[c2 * 4 + j]), acc);
        lgb[row * 4 + j] = acc;
    }
    __syncthreads();
    if (tid < ROWS) {
        const float l0 = lgb[tid * 4 + 0], l1 = lgb[tid * 4 + 1];
        const float l2 = lgb[tid * 4 + 2], l3 = lgb[tid * 4 + 3];
        const float m  = fmaxf(fmaxf(l0, l1), fmaxf(l2, l3));
        const float e0f = __expf(l0 - m), e1f = __expf(l1 - m);
        const float e2f = __expf(l2 - m), e3f = __expf(l3 - m);
        const float inv = 1.0f / (e0f + e1f + e2f + e3f);
        gwb[tid * 4 + 0] = e0f * inv; gwb[tid * 4 + 1] = e1f * inv;
        gwb[tid * 4 + 2] = e2f * inv; gwb[tid * 4 + 3] = e3f * inv;
    }
    // published by next step's barrier

    // ---- expert loop: 6 ring steps per expert ------------------------------
    int cur = 0;   // buf holding the next chunk to consume (W1[e0]c0 in buf0)
    const int lrow_q = tid >> 2;
    const int cq     = (tid & 3) * 16;
    float agv[16];
#pragma unroll 1
    for (int ep = 0; ep < 4; ep++) {
        const int e = (ep < 2) ? ep : (ep + 2 * g);
        const __nv_bfloat16* w1img = g_wimg + IW1 + e * 32768;

        float acc1[2][4][4];
#pragma unroll
        for (int mt = 0; mt < 2; mt++)
#pragma unroll
            for (int nt = 0; nt < 4; nt++)
#pragma unroll
                for (int i = 0; i < 4; i++) acc1[mt][nt][i] = 0.f;

        // W1 c0..c3 (64-K chunks)
#pragma unroll
        for (int c = 0; c < 4; c++) {
            cp_wait0(); __syncthreads();
            if (c < 3)
                stage_chunk<128, 8, 32>(wstA[cur ^ 1], w1img, c + 1, tid);
            else
                stage_chunk<64, 16, 16>(wstA[cur ^ 1], g_wimg + IW2 + e * 8192, 0, tid);
            mma_chunk<128, 64, P_CM>(acc1, cmw, wstA[cur], c, tid);
            cur ^= 1;
        }
        epilogue<128, true, true, P_A>(acc1, exp_b1 + e * 128, aw, tid);

        // W2 (full K=128 in one buffer)
        float acc2[1][4][4];
#pragma unroll
        for (int nt = 0; nt < 4; nt++)
#pragma unroll
            for (int i = 0; i < 4; i++) acc2[0][nt][i] = 0.f;
        cp_wait0(); __syncthreads();          // W2 staged + aw published
        stage_chunk<64, 8, 8>(wstA[cur ^ 1], g_wimg + IW3 + e * 4096, 0, tid);
        mma_chunk<64, 128, P_A>(acc2, aw, wstA[cur], 0, tid);
        cur ^= 1;
        epilogue<64, true, true, P_B>(acc2, exp_b2 + e * 64, bw, tid);

        // W3 (64-K)
        float acc3[1][4][4];
#pragma unroll
        for (int nt = 0; nt < 4; nt++)
#pragma unroll
            for (int i = 0; i < 4; i++) acc3[0][nt][i] = 0.f;
        cp_wait0(); __syncthreads();          // W3 staged + bw published
        if (ep < 3) {
            const int en = (ep + 1 < 2) ? (ep + 1) : (ep + 1 + 2 * g);
            stage_chunk<128, 8, 32>(wstA[cur ^ 1], g_wimg + IW1 + en * 32768, 0, tid);
        } else {
            stage_chunk<64, 8, 8, false>(wstA[cur ^ 1], g_wimg + IT1 + t * 4096, 0, tid);
            stage_small<32, 8, 8>(wstA[cur ^ 1] + SUB_OFF, g_wimg + IT2 + t * 2048, tid);
            cp_commit();
        }
        mma_chunk<64, 64, P_B>(acc3, bw, wstA[cur], 0, tid);
        cur ^= 1;
        epilogue<64, false, false, P_CF>(acc3, exp_b3 + e * 64, cfp, tid);
        __syncthreads();                      // publish cfp for LN

        // fast LN + diag self-gate + softmax aggregation
        {
            const float* lS  = ln_s + e * 64 + cq;
            const float* lB  = ln_b + e * 64 + cq;
            const float* sgw = sg_W + (size_t)t * 256;
            const float  sgb = __ldg(&sg_b[t * 4 + ep]);
            const float* src = &cfp[lrow_q * P_CF + cq];
            float n[16];
            float sum = 0.f, sq = 0.f;
#pragma unroll
            for (int i = 0; i < 16; i += 2) {
                const float2 v2 = *reinterpret_cast<const float2*>(src + i);
                n[i] = v2.x; n[i + 1] = v2.y;
                sum += v2.x + v2.y;
                sq = fmaf(v2.x, v2.x, fmaf(v2.y, v2.y, sq));
            }
            sum += __shfl_xor_sync(0xffffffffu, sum, 1);
            sq  += __shfl_xor_sync(0xffffffffu, sq,  1);
            sum += __shfl_xor_sync(0xffffffffu, sum, 2);
            sq  += __shfl_xor_sync(0xffffffffu, sq,  2);
            const float mu  = sum * (1.0f / 64.0f);
            const float var = sq * (1.0f / 64.0f) - mu * mu;
            const float inv = rsqrtf(var + 1e-5f);
            float swp = 0.f;
#pragma unroll
            for (int i = 0; i < 16; i++) {
                n[i] = fmaf((n[i] - mu) * inv, __ldg(&lS[i]), __ldg(&lB[i]));
                swp = fmaf(n[i], __ldg(&sgw[(cq + i) * 4 + ep]), swp);
            }
            swp += __shfl_xor_sync(0xffffffffu, swp, 1);
            swp += __shfl_xor_sync(0xffffffffu, swp, 2);
            const float scale = (swp + sgb) * gwb[lrow_q * 4 + ep];
            if (ep == 0) {
#pragma unroll
                for (int i = 0; i < 16; i++) agv[i] = n[i] * scale;
            } else {
#pragma unroll
                for (int i = 0; i < 16; i++) agv[i] = fmaf(n[i], scale, agv[i]);
            }
        }
    }

    // ---- agg -> bf16 bw -----------------------------------------------------
    {
        uint4 o0, o1;
        o0.x = packbf(agv[0], agv[1]);   o0.y = packbf(agv[2], agv[3]);
        o0.z = packbf(agv[4], agv[5]);   o0.w = packbf(agv[6], agv[7]);
        o1.x = packbf(agv[8], agv[9]);   o1.y = packbf(agv[10], agv[11]);
        o1.z = packbf(agv[12], agv[13]); o1.w = packbf(agv[14], agv[15]);
        uint4* dst = reinterpret_cast<uint4*>(&bw[lrow_q * P_B + (tid & 3) * 8]);
        dst[0] = o0; dst[1] = o1;
    }

    // ---- tower layer 1 (T1/T2 already in flight in buf `cur`) ---------------
    {
        float accU[1][4][4];
#pragma unroll
        for (int nt = 0; nt < 4; nt++)
#pragma unroll
            for (int i = 0; i < 4; i++) accU[0][nt][i] = 0.f;
        cp_wait0(); __syncthreads();   // T1+T2 staged + bw published
        mma_chunk<64, 64, P_B>(accU, bw, wstA[cur], 0, tid);
        epilogue<64, true, true, P_A>(accU, tw_b1 + t * 64, aw, tid);
    }
    __syncthreads();   // publish aw (bf16 tower h1)

    // ---- tower layer 2 via mma (N=32, K=64) --------------------------------
    {
        const int col0  = (wid & 1) * 16;
        const int mrow0 = (wid >> 1) * 16;
        const int lrow = lane & 7, lg8 = (lane >> 3) & 1, lg16 = lane >> 4;
        const uint32_t a0 = sm_addr(aw) +
            ((mrow0 + lg8 * 8 + lrow) * P_A + lg16 * 4) * 4;
        const uint32_t b0 = wstA[cur] + SUB_OFF +
            (uint32_t)(col0 + lg16 * 8 + lrow) * 144 + lg8 * 16;
        float acc[2][4];
#pragma unroll
        for (int nt = 0; nt < 2; nt++)
#pragma unroll
            for (int i = 0; i < 4; i++) acc[nt][i] = 0.f;
#pragma unroll
        for (int ks = 0; ks < 4; ks++) {
            uint32_t af[4];
            ldsm4(af[0], af[1], af[2], af[3], a0 + ks * 32);
            uint32_t bf[4];
            ldsm4(bf[0], bf[1], bf[2], bf[3], b0 + ks * 32);
            mma16(acc[0], af, bf[0], bf[1]);
            mma16(acc[1], af, bf[2], bf[3]);
        }
        const int r = lane >> 2, c = lane & 3;
#pragma unroll
        for (int nt = 0; nt < 2; nt++) {
            const int cn = col0 + nt * 8 + 2 * c;
            const float bb0 = __ldg(&tw_b2[t * 32 + cn]);
            const float bb1 = __ldg(&tw_b2[t * 32 + cn + 1]);
            twh2[(mrow0 + r) * P_B + cn]     = swishf(acc[nt][0] + bb0);
            twh2[(mrow0 + r) * P_B + cn + 1] = swishf(acc[nt][1] + bb1);
            twh2[(mrow0 + r + 8) * P_B + cn]     = swishf(acc[nt][2] + bb0);
            twh2[(mrow0 + r + 8) * P_B + cn + 1] = swishf(acc[nt][3] + bb1);
        }
    }
    __syncthreads();
    if (tid < ROWS) {
        const float* th = &twh2[tid * P_B];
        const float* W  = tw_W3 + t * 32;
        float acc = __ldg(&tw_b3[t]);
#pragma unroll 4
        for (int c2 = 0; c2 < 32; c2++)
            acc = fmaf(th[c2], __ldg(&W[c2]), acc);
        out[(size_t)(row0 + tid) * 4 + t] = sigm(acc);
    }
}

extern "C" void kernel_launch(void* const* d_in, const int* in_sizes, int n_in,
                              void* d_out, int out_size)
{
    (void)n_in; (void)out_size;
    const float* zs   = (const float*)d_in[0];
    const float* z0   = (const float*)d_in[1];
    const float* z1   = (const float*)d_in[2];
    const float* eW1  = (const float*)d_in[4];
    const float* eb1  = (const float*)d_in[5];
    const float* eW2  = (const float*)d_in[6];
    const float* eb2  = (const float*)d_in[7];
    const float* eW3  = (const float*)d_in[8];
    const float* eb3  = (const float*)d_in[9];
    const float* lns  = (const float*)d_in[10];
    const float* lnb  = (const float*)d_in[11];
    const float* fgA  = (const float*)d_in[12];
    const float* fgB  = (const float*)d_in[13];
    const float* tgW1 = (const float*)d_in[14];
    const float* tgb1 = (const float*)d_in[15];
    const float* tgW2 = (const float*)d_in[16];
    const float* tgb2 = (const float*)d_in[17];
    const float* sgW  = (const float*)d_in[18];
    const float* sgb  = (const float*)d_in[19];
    const float* twW1 = (const float*)d_in[20];
    const float* twb1 = (const float*)d_in[21];
    const float* twW2 = (const float*)d_in[22];
    const float* twb2 = (const float*)d_in[23];
    const float* twW3 = (const float*)d_in[24];
    const float* twb3 = (const float*)d_in[25];

    const int Bn = in_sizes[0] / META;

    prep_all<<<296, 256>>>(eW1, eW2, eW3, tgW1, twW1, fgA, fgB, twW2);

    cudaFuncSetAttribute(home_kernel, cudaFuncAttributeMaxDynamicSharedMemorySize,
                         SMEM_TOTAL);
    dim3 grid(Bn / ROWS, 4);
    home_kernel<<<grid, THREADS, SMEM_TOTAL>>>(
        zs, z0, z1, eb1, eb2, eb3, lns, lnb,
        tgb1, tgW2, tgb2, sgW, sgb, twb1, twb2, twW3, twb3,
        (float*)d_out);
}